// round 3
// baseline (speedup 1.0000x reference)
#include <cuda_runtime.h>
#include <math.h>
#include <stdint.h>

// Problem constants
#define T   2048
#define Dm  512
#define H   8
#define DH  64
#define CH  128          // chunk length
#define NC  (T / CH)     // 16 chunks
#define STATS_STRIDE (DH*DH + DH)  // 4160 floats per (head,chunk): [KV 64x64 | ksum 64]

// Scratch (device globals — no allocation allowed)
__device__ float g_Qp[H * T * DH];
__device__ float g_Kp[H * T * DH];
__device__ float g_V [H * T * DH];
__device__ float g_stats[H * NC * STATS_STRIDE];
__device__ float g_pref [H * NC * STATS_STRIDE];
__device__ float g_O [T * Dm];

// ---------------------------------------------------------------------------
// TF32 tensor-core GEMM (mma.sync.m16n8k8, 3-term split):
//   C += Ahi*Bhi + Alo*Bhi + Ahi*Blo
// Tile BM=128, BN=64, BK=32. 256 threads = 8 warps (4 M x 2 N),
// warp tile 32x32 = 2 m x 4 n of m16n8.
// smem holds PRE-SPLIT (hi,lo) pairs as float2; double-buffered with
// register prefetch of the next global K-slab.
// ---------------------------------------------------------------------------
#define A_STR 36                  // float2 per A row (32 + 4 pad)
#define B_STR 68                  // float2 per B row (64 + 4 pad)
#define A_F2  (128 * A_STR)       // 4608
#define B_F2  (32 * B_STR)        // 2176
#define BUF_F2 (A_F2 + B_F2)      // 6784 float2 per buffer
#define GEMM_SMEM (2 * BUF_F2 * (int)sizeof(float2))   // 108544 B
#define C_STR 68                  // floats per epilogue row (64 + 4 pad)

__device__ __forceinline__ uint32_t f2tf32(float x) {
    uint32_t r;
    asm("cvt.rna.tf32.f32 %0, %1;" : "=r"(r) : "f"(x));
    return r;
}

__device__ __forceinline__ float2 split_tf32(float f) {
    uint32_t hi = f2tf32(f);
    float hif = __uint_as_float(hi);
    uint32_t lo = f2tf32(f - hif);
    return make_float2(hif, __uint_as_float(lo));
}

__device__ __forceinline__ void mma8(float c[4], const uint32_t a[4], const uint32_t b[2]) {
    asm volatile(
        "mma.sync.aligned.m16n8k8.row.col.f32.tf32.tf32.f32 "
        "{%0,%1,%2,%3}, {%4,%5,%6,%7}, {%8,%9}, {%0,%1,%2,%3};"
        : "+f"(c[0]), "+f"(c[1]), "+f"(c[2]), "+f"(c[3])
        : "r"(a[0]), "r"(a[1]), "r"(a[2]), "r"(a[3]),
          "r"(b[0]), "r"(b[1]));
}

// Stage a prefetched K-slab (A:128x32, B:32x64 floats) into buffer `buf`,
// splitting each element into (hi,lo).
__device__ __forceinline__ void stage_slab(float2* __restrict__ buf,
                                           const float4 ra[4], const float4 rb[2],
                                           int tid)
{
    float2* As = buf;
    float2* Bs = buf + A_F2;
    #pragma unroll
    for (int i = 0; i < 4; i++) {
        int slot = tid + i * 256;
        int r = slot >> 3, c4 = (slot & 7) << 2;
        float2* p = &As[r * A_STR + c4];
        p[0] = split_tf32(ra[i].x);
        p[1] = split_tf32(ra[i].y);
        p[2] = split_tf32(ra[i].z);
        p[3] = split_tf32(ra[i].w);
    }
    #pragma unroll
    for (int i = 0; i < 2; i++) {
        int slot = tid + i * 256;
        int r = slot >> 4, c4 = (slot & 15) << 2;
        float2* p = &Bs[r * B_STR + c4];
        p[0] = split_tf32(rb[i].x);
        p[1] = split_tf32(rb[i].y);
        p[2] = split_tf32(rb[i].z);
        p[3] = split_tf32(rb[i].w);
    }
}

__device__ __forceinline__ void load_slab(const float* __restrict__ A,
                                          const float* __restrict__ B,
                                          int row0, int col0, int k0,
                                          float4 ra[4], float4 rb[2], int tid)
{
    #pragma unroll
    for (int i = 0; i < 4; i++) {
        int slot = tid + i * 256;
        int r = slot >> 3, c4 = (slot & 7) << 2;
        ra[i] = *(const float4*)&A[(row0 + r) * Dm + k0 + c4];
    }
    #pragma unroll
    for (int i = 0; i < 2; i++) {
        int slot = tid + i * 256;
        int r = slot >> 4, c4 = (slot & 15) << 2;
        rb[i] = *(const float4*)&B[(k0 + r) * Dm + col0 + c4];
    }
}

// Full-K (512) GEMM into acc[2][4][4].
__device__ __forceinline__ void gemm_body(const float* __restrict__ A,
                                          const float* __restrict__ B,
                                          int row0, int col0,
                                          float acc[2][4][4],
                                          float2* sm)
{
    const int tid  = threadIdx.x;
    const int lane = tid & 31;
    const int wid  = tid >> 5;
    const int wm   = (wid & 3) * 32;
    const int wn   = (wid >> 2) * 32;
    const int lr   = lane >> 2;   // 0..7
    const int lc   = lane & 3;    // 0..3

    #pragma unroll
    for (int mt = 0; mt < 2; mt++)
        #pragma unroll
        for (int nt = 0; nt < 4; nt++)
            #pragma unroll
            for (int i = 0; i < 4; i++) acc[mt][nt][i] = 0.f;

    float4 ra[4]; float4 rb[2];
    load_slab(A, B, row0, col0, 0, ra, rb, tid);
    stage_slab(sm, ra, rb, tid);
    __syncthreads();

    int cur = 0;
    for (int k0 = 0; k0 < Dm; k0 += 32) {
        const bool has_next = (k0 + 32 < Dm);
        if (has_next) load_slab(A, B, row0, col0, k0 + 32, ra, rb, tid);

        const float2* Ab = sm + cur * BUF_F2;
        const float2* Bb = Ab + A_F2;

        #pragma unroll
        for (int kk = 0; kk < 4; kk++) {
            const int kb = kk * 8;

            uint32_t ah[2][4], al[2][4];
            #pragma unroll
            for (int mt = 0; mt < 2; mt++) {
                int r = wm + mt * 16 + lr;
                float2 p0 = Ab[ r      * A_STR + kb + lc];
                float2 p1 = Ab[(r + 8) * A_STR + kb + lc];
                float2 p2 = Ab[ r      * A_STR + kb + lc + 4];
                float2 p3 = Ab[(r + 8) * A_STR + kb + lc + 4];
                ah[mt][0] = __float_as_uint(p0.x); al[mt][0] = __float_as_uint(p0.y);
                ah[mt][1] = __float_as_uint(p1.x); al[mt][1] = __float_as_uint(p1.y);
                ah[mt][2] = __float_as_uint(p2.x); al[mt][2] = __float_as_uint(p2.y);
                ah[mt][3] = __float_as_uint(p3.x); al[mt][3] = __float_as_uint(p3.y);
            }
            uint32_t bh[4][2], bl[4][2];
            #pragma unroll
            for (int nt = 0; nt < 4; nt++) {
                int n = wn + nt * 8 + lr;
                float2 q0 = Bb[(kb + lc)     * B_STR + n];
                float2 q1 = Bb[(kb + lc + 4) * B_STR + n];
                bh[nt][0] = __float_as_uint(q0.x); bl[nt][0] = __float_as_uint(q0.y);
                bh[nt][1] = __float_as_uint(q1.x); bl[nt][1] = __float_as_uint(q1.y);
            }
            #pragma unroll
            for (int mt = 0; mt < 2; mt++)
                #pragma unroll
                for (int nt = 0; nt < 4; nt++) {
                    mma8(acc[mt][nt], ah[mt], bh[nt]);
                    mma8(acc[mt][nt], al[mt], bh[nt]);
                    mma8(acc[mt][nt], ah[mt], bl[nt]);
                }
        }

        if (has_next) stage_slab(sm + (1 - cur) * BUF_F2, ra, rb, tid);
        __syncthreads();
        cur ^= 1;
    }
}

// Store acc into padded smem tile (conflict-free), for coalesced writeback.
__device__ __forceinline__ void acc_to_smem(float* Cs, const float acc[2][4][4])
{
    const int lane = threadIdx.x & 31;
    const int wid  = threadIdx.x >> 5;
    const int wm   = (wid & 3) * 32;
    const int wn   = (wid >> 2) * 32;
    const int lr = lane >> 2, lc = lane & 3;

    #pragma unroll
    for (int mt = 0; mt < 2; mt++)
        #pragma unroll
        for (int nt = 0; nt < 4; nt++) {
            int r = wm + mt * 16 + lr;
            int n = wn + nt * 8 + 2 * lc;
            #pragma unroll
            for (int i = 0; i < 4; i++)
                Cs[(r + (i >= 2 ? 8 : 0)) * C_STR + n + (i & 1)] = acc[2 > 1 ? mt : 0][nt][i];
        }
}

// ---------------------------------------------------------------------------
// Kernel 1: fused QKV projection. grid = (T/128, H, 3).
// ---------------------------------------------------------------------------
__global__ void __launch_bounds__(256) qkv_mma_kernel(
    const float* __restrict__ x,
    const float* __restrict__ Wq, const float* __restrict__ bq,
    const float* __restrict__ Wk, const float* __restrict__ bk,
    const float* __restrict__ Wv, const float* __restrict__ bv)
{
    extern __shared__ float2 sm2[];

    const int which = blockIdx.z;
    const float* W = (which == 0) ? Wq : (which == 1) ? Wk : Wv;
    const float* b = (which == 0) ? bq : (which == 1) ? bk : bv;
    float* out = (which == 0) ? g_Qp : (which == 1) ? g_Kp : g_V;

    const int row0 = blockIdx.x * 128;
    const int h    = blockIdx.y;
    const int col0 = h * 64;

    float acc[2][4][4];
    gemm_body(x, W, row0, col0, acc, sm2);

    // epilogue via smem for coalesced stores
    float* Cs = (float*)sm2;
    acc_to_smem(Cs, acc);
    __syncthreads();

    const int tid = threadIdx.x;
    #pragma unroll
    for (int it = 0; it < 8; it++) {
        int idx = tid + it * 256;          // 2048 float4 slots
        int r = idx >> 4, c4 = (idx & 15) << 2;
        float4 v = *(float4*)&Cs[r * C_STR + c4];
        v.x += b[col0 + c4 + 0];
        v.y += b[col0 + c4 + 1];
        v.z += b[col0 + c4 + 2];
        v.w += b[col0 + c4 + 3];
        if (which < 2) {
            v.x = (v.x > 0.f) ? (v.x + 1.f) : expf(v.x);
            v.y = (v.y > 0.f) ? (v.y + 1.f) : expf(v.y);
            v.z = (v.z > 0.f) ? (v.z + 1.f) : expf(v.z);
            v.w = (v.w > 0.f) ? (v.w + 1.f) : expf(v.w);
        }
        *(float4*)&out[((h * T + row0 + r) << 6) + c4] = v;
    }
}

// ---------------------------------------------------------------------------
// Kernel 2: per-(head,chunk) stats: KV = Kp_chunk^T @ V_chunk, ksum.
// ---------------------------------------------------------------------------
__global__ void chunk_kernel()
{
    __shared__ float Ks[32 * 65];
    __shared__ float Vs[32 * 65];

    const int c = blockIdx.x, h = blockIdx.y;
    const int tid = threadIdx.x;
    const int tx = tid & 15, ty = tid >> 4;

    const float* Kbase = g_Kp + ((h * T + c * CH) << 6);
    const float* Vbase = g_V  + ((h * T + c * CH) << 6);

    float acc[4][4];
    #pragma unroll
    for (int i = 0; i < 4; i++)
        #pragma unroll
        for (int j = 0; j < 4; j++) acc[i][j] = 0.f;
    float ks = 0.f;

    for (int sl = 0; sl < 4; sl++) {
        #pragma unroll
        for (int i = 0; i < 8; i++) {
            int idx = tid + i * 256;
            int s = idx >> 6, d = idx & 63;
            Ks[s * 65 + d] = Kbase[((sl * 32 + s) << 6) + d];
            Vs[s * 65 + d] = Vbase[((sl * 32 + s) << 6) + d];
        }
        __syncthreads();
        #pragma unroll
        for (int s = 0; s < 32; s++) {
            float a[4], bb[4];
            #pragma unroll
            for (int i = 0; i < 4; i++) a[i] = Ks[s * 65 + ty * 4 + i];
            #pragma unroll
            for (int j = 0; j < 4; j++) bb[j] = Vs[s * 65 + tx * 4 + j];
            #pragma unroll
            for (int i = 0; i < 4; i++)
                #pragma unroll
                for (int j = 0; j < 4; j++) acc[i][j] += a[i] * bb[j];
        }
        if (tid < 64) {
            #pragma unroll
            for (int s = 0; s < 32; s++) ks += Ks[s * 65 + tid];
        }
        __syncthreads();
    }

    float* outp = g_stats + (h * NC + c) * STATS_STRIDE;
    #pragma unroll
    for (int i = 0; i < 4; i++)
        #pragma unroll
        for (int j = 0; j < 4; j++)
            outp[(ty * 4 + i) * 64 + tx * 4 + j] = acc[i][j];
    if (tid < 64) outp[4096 + tid] = ks;
}

// ---------------------------------------------------------------------------
// Kernel 3: exclusive prefix over chunks (per head).
// ---------------------------------------------------------------------------
__global__ void prefix_kernel()
{
    const int h = blockIdx.x;
    for (int e = threadIdx.x; e < STATS_STRIDE; e += 256) {
        float run = 0.f;
        for (int c = 0; c < NC; c++) {
            g_pref [(h * NC + c) * STATS_STRIDE + e] = run;
            run +=  g_stats[(h * NC + c) * STATS_STRIDE + e];
        }
    }
}

// ---------------------------------------------------------------------------
// Kernel 4: per-(head,chunk) attention output.
// ---------------------------------------------------------------------------
__global__ void __launch_bounds__(256, 1) attn_kernel()
{
    extern __shared__ float sm[];
    float* Qs   = sm;                    // 128*65
    float* Ks   = Qs + 128 * 65;         // 128*65
    float* Vs   = Ks + 128 * 65;         // 128*65
    float* Ss   = Vs + 128 * 65;         // 64*65
    float* zs   = Ss + 64 * 65;          // 64
    float* Am   = zs + 64;               // 128*129
    float* dens = Am + 128 * 129;        // 128

    const int c = blockIdx.x, h = blockIdx.y;
    const int tid = threadIdx.x;

    const float* Qbase = g_Qp + ((h * T + c * CH) << 6);
    const float* Kbase = g_Kp + ((h * T + c * CH) << 6);
    const float* Vbase = g_V  + ((h * T + c * CH) << 6);
    const float* P     = g_pref + (h * NC + c) * STATS_STRIDE;

    #pragma unroll
    for (int i = 0; i < 32; i++) {
        int idx = tid + i * 256;
        int t = idx >> 6, d = idx & 63;
        Qs[t * 65 + d] = Qbase[idx];
        Ks[t * 65 + d] = Kbase[idx];
        Vs[t * 65 + d] = Vbase[idx];
    }
    #pragma unroll
    for (int i = 0; i < 16; i++) {
        int idx = tid + i * 256;
        int r = idx >> 6, d = idx & 63;
        Ss[r * 65 + d] = P[idx];
    }
    if (tid < 64) zs[tid] = P[4096 + tid];
    __syncthreads();

    // Phase A: A[t][s] = (s<=t) ? Qp[t].Kp[s] : 0
    {
        const int ti = tid >> 4, tj = tid & 15;
        float a[8][8];
        #pragma unroll
        for (int i = 0; i < 8; i++)
            #pragma unroll
            for (int j = 0; j < 8; j++) a[i][j] = 0.f;
        for (int k = 0; k < 64; k++) {
            float qa[8], kb[8];
            #pragma unroll
            for (int i = 0; i < 8; i++) qa[i] = Qs[(ti * 8 + i) * 65 + k];
            #pragma unroll
            for (int j = 0; j < 8; j++) kb[j] = Ks[(tj * 8 + j) * 65 + k];
            #pragma unroll
            for (int i = 0; i < 8; i++)
                #pragma unroll
                for (int j = 0; j < 8; j++) a[i][j] += qa[i] * kb[j];
        }
        #pragma unroll
        for (int i = 0; i < 8; i++) {
            int t = ti * 8 + i;
            #pragma unroll
            for (int j = 0; j < 8; j++) {
                int s = tj * 8 + j;
                Am[t * 129 + s] = (s <= t) ? a[i][j] : 0.f;
            }
        }
    }
    __syncthreads();

    if (tid < 128) {
        int t = tid;
        float d = 0.f;
        for (int i = 0; i < 64; i++) d += Qs[t * 65 + i] * zs[i];
        for (int s = 0; s < 128; s++) d += Am[t * 129 + s];
        dens[t] = fmaxf(d, 1e-6f);
    }
    __syncthreads();

    // Phase B
    {
        const int ti = tid >> 4, tj = tid & 15;
        float acc[8][4];
        #pragma unroll
        for (int r = 0; r < 8; r++)
            #pragma unroll
            for (int j = 0; j < 4; j++) acc[r][j] = 0.f;

        for (int i = 0; i < 64; i++) {
            float q[8], s4[4];
            #pragma unroll
            for (int r = 0; r < 8; r++) q[r] = Qs[(ti * 8 + r) * 65 + i];
            #pragma unroll
            for (int j = 0; j < 4; j++) s4[j] = Ss[i * 65 + tj * 4 + j];
            #pragma unroll
            for (int r = 0; r < 8; r++)
                #pragma unroll
                for (int j = 0; j < 4; j++) acc[r][j] += q[r] * s4[j];
        }
        for (int s = 0; s < 128; s++) {
            float a8[8], v4[4];
            #pragma unroll
            for (int r = 0; r < 8; r++) a8[r] = Am[(ti * 8 + r) * 129 + s];
            #pragma unroll
            for (int j = 0; j < 4; j++) v4[j] = Vs[s * 65 + tj * 4 + j];
            #pragma unroll
            for (int r = 0; r < 8; r++)
                #pragma unroll
                for (int j = 0; j < 4; j++) acc[r][j] += a8[r] * v4[j];
        }

        float* Ob = g_O + (c * CH) * Dm + h * DH;
        #pragma unroll
        for (int r = 0; r < 8; r++) {
            int t = ti * 8 + r;
            float inv = 1.f / dens[t];
            #pragma unroll
            for (int j = 0; j < 4; j++)
                Ob[t * Dm + tj * 4 + j] = acc[r][j] * inv;
        }
    }
}

// ---------------------------------------------------------------------------
// Kernel 5: output projection.  grid = (T/128, Dm/64)
// ---------------------------------------------------------------------------
__global__ void __launch_bounds__(256) out_mma_kernel(
    const float* __restrict__ Wo,
    const float* __restrict__ bo,
    float* __restrict__ y)
{
    extern __shared__ float2 sm2[];

    const int row0 = blockIdx.x * 128;
    const int col0 = blockIdx.y * 64;

    float acc[2][4][4];
    gemm_body(g_O, Wo, row0, col0, acc, sm2);

    float* Cs = (float*)sm2;
    acc_to_smem(Cs, acc);
    __syncthreads();

    const int tid = threadIdx.x;
    #pragma unroll
    for (int it = 0; it < 8; it++) {
        int idx = tid + it * 256;
        int r = idx >> 4, c4 = (idx & 15) << 2;
        float4 v = *(float4*)&Cs[r * C_STR + c4];
        v.x += bo[col0 + c4 + 0];
        v.y += bo[col0 + c4 + 1];
        v.z += bo[col0 + c4 + 2];
        v.w += bo[col0 + c4 + 3];
        *(float4*)&y[(row0 + r) * Dm + col0 + c4] = v;
    }
}

// ---------------------------------------------------------------------------
extern "C" void kernel_launch(void* const* d_in, const int* in_sizes, int n_in,
                              void* d_out, int out_size)
{
    const float* x  = (const float*)d_in[0];
    const float* Wq = (const float*)d_in[1];
    const float* bq = (const float*)d_in[2];
    const float* Wk = (const float*)d_in[3];
    const float* bk = (const float*)d_in[4];
    const float* Wv = (const float*)d_in[5];
    const float* bv = (const float*)d_in[6];
    const float* Wo = (const float*)d_in[7];
    const float* bo = (const float*)d_in[8];
    float* y = (float*)d_out;

    const int SMEM_ATTN = (128*65*3 + 64*65 + 64 + 128*129 + 128) * 4; // 183296 B
    cudaFuncSetAttribute(attn_kernel,
                         cudaFuncAttributeMaxDynamicSharedMemorySize, SMEM_ATTN);
    cudaFuncSetAttribute(qkv_mma_kernel,
                         cudaFuncAttributeMaxDynamicSharedMemorySize, GEMM_SMEM);
    cudaFuncSetAttribute(out_mma_kernel,
                         cudaFuncAttributeMaxDynamicSharedMemorySize, GEMM_SMEM);

    qkv_mma_kernel<<<dim3(T/128, H, 3), 256, GEMM_SMEM>>>(x, Wq, bq, Wk, bk, Wv, bv);
    chunk_kernel  <<<dim3(NC, H), 256>>>();
    prefix_kernel <<<H, 256>>>();
    attn_kernel   <<<dim3(NC, H), 256, SMEM_ATTN>>>();
    out_mma_kernel<<<dim3(T/128, Dm/64), 256, GEMM_SMEM>>>(Wo, bo, y);
}

// round 4
// speedup vs baseline: 1.6441x; 1.6441x over previous
#include <cuda_runtime.h>
#include <cuda_bf16.h>
#include <math.h>
#include <stdint.h>

// Problem constants
#define T   2048
#define Dm  512
#define H   8
#define DH  64
#define CH  128
#define NC  (T / CH)
#define STATS_STRIDE (DH*DH + DH)   // 4160

// Scratch (device globals — no allocation allowed)
__device__ float g_Qp[H * T * DH];
__device__ float g_Kp[H * T * DH];
__device__ float g_V [H * T * DH];
__device__ float g_stats[H * NC * STATS_STRIDE];
__device__ float g_pref [H * NC * STATS_STRIDE];
__device__ float g_O [T * Dm];

// ---------------------------------------------------------------------------
// bf16 split tensor-core GEMM: C += Ahi*Bhi + Alo*Bhi + Ahi*Blo
// mma.m16n8k16. Tile BM=128, BN=64, BK=32. 256 threads = 8 warps (4M x 2N),
// warp tile 32x32. smem: pre-split bf16 hi/lo planes; A k-major, B n-major
// (transposed at staging). Stride 40 bf16 per row -> conflict-free frags.
// Double-buffered (61KB total).
// ---------------------------------------------------------------------------
#define A_STR 40
#define AHI 0
#define ALO (128 * A_STR)                 // 5120
#define BHI (2 * 128 * A_STR)             // 10240
#define BLO (BHI + 64 * A_STR)            // 12800
#define BUF_E (BHI + 2 * 64 * A_STR)      // 15360 bf16 per buffer
#define GEMM_SMEM (2 * BUF_E * (int)sizeof(__nv_bfloat16))  // 61440 B
#define C_STR 68

__device__ __forceinline__ uint32_t pack_bf2(float a, float b) {
    __nv_bfloat162 t;
    t.x = __float2bfloat16_rn(a);
    t.y = __float2bfloat16_rn(b);
    return *(uint32_t*)&t;
}

__device__ __forceinline__ void mma16(float c[4], const uint32_t a[4], const uint32_t b[2]) {
    asm volatile(
        "mma.sync.aligned.m16n8k16.row.col.f32.bf16.bf16.f32 "
        "{%0,%1,%2,%3}, {%4,%5,%6,%7}, {%8,%9}, {%0,%1,%2,%3};"
        : "+f"(c[0]), "+f"(c[1]), "+f"(c[2]), "+f"(c[3])
        : "r"(a[0]), "r"(a[1]), "r"(a[2]), "r"(a[3]),
          "r"(b[0]), "r"(b[1]));
}

__device__ __forceinline__ void load_slab(const float* __restrict__ A,
                                          const float* __restrict__ B,
                                          int row0, int col0, int k0,
                                          float4 ra[4], float4 rb[2], int tid)
{
    #pragma unroll
    for (int i = 0; i < 4; i++) {
        int slot = tid + i * 256;
        int r = slot >> 3, c4 = (slot & 7) << 2;
        ra[i] = *(const float4*)&A[(row0 + r) * Dm + k0 + c4];
    }
    #pragma unroll
    for (int i = 0; i < 2; i++) {
        int slot = tid + i * 256;
        int r = slot >> 4, c4 = (slot & 15) << 2;
        rb[i] = *(const float4*)&B[(k0 + r) * Dm + col0 + c4];
    }
}

__device__ __forceinline__ void stage_slab(__nv_bfloat16* __restrict__ buf,
                                           const float4 ra[4], const float4 rb[2],
                                           int tid)
{
    #pragma unroll
    for (int i = 0; i < 4; i++) {
        int slot = tid + i * 256;
        int r = slot >> 3, c4 = (slot & 7) << 2;
        float x0 = ra[i].x, x1 = ra[i].y, x2 = ra[i].z, x3 = ra[i].w;
        float h0 = __bfloat162float(__float2bfloat16_rn(x0));
        float h1 = __bfloat162float(__float2bfloat16_rn(x1));
        float h2 = __bfloat162float(__float2bfloat16_rn(x2));
        float h3 = __bfloat162float(__float2bfloat16_rn(x3));
        uint2 ph = make_uint2(pack_bf2(h0, h1), pack_bf2(h2, h3));
        uint2 pl = make_uint2(pack_bf2(x0 - h0, x1 - h1), pack_bf2(x2 - h2, x3 - h3));
        *(uint2*)&buf[AHI + r * A_STR + c4] = ph;
        *(uint2*)&buf[ALO + r * A_STR + c4] = pl;
    }
    #pragma unroll
    for (int i = 0; i < 2; i++) {
        int slot = tid + i * 256;
        int r = slot >> 4, c4 = (slot & 15) << 2;
        float x[4] = {rb[i].x, rb[i].y, rb[i].z, rb[i].w};
        #pragma unroll
        for (int j = 0; j < 4; j++) {
            __nv_bfloat16 hb = __float2bfloat16_rn(x[j]);
            float hf = __bfloat162float(hb);
            buf[BHI + (c4 + j) * A_STR + r] = hb;
            buf[BLO + (c4 + j) * A_STR + r] = __float2bfloat16_rn(x[j] - hf);
        }
    }
}

// Full-K (512) GEMM into acc[2][4][4].
__device__ __forceinline__ void gemm_body(const float* __restrict__ A,
                                          const float* __restrict__ B,
                                          int row0, int col0,
                                          float acc[2][4][4],
                                          __nv_bfloat16* sm)
{
    const int tid  = threadIdx.x;
    const int lane = tid & 31;
    const int wid  = tid >> 5;
    const int wm   = (wid & 3) * 32;
    const int wn   = (wid >> 2) * 32;
    const int lr   = lane >> 2;   // 0..7
    const int lc   = lane & 3;    // 0..3

    #pragma unroll
    for (int mt = 0; mt < 2; mt++)
        #pragma unroll
        for (int nt = 0; nt < 4; nt++)
            #pragma unroll
            for (int i = 0; i < 4; i++) acc[mt][nt][i] = 0.f;

    float4 ra[4]; float4 rb[2];
    load_slab(A, B, row0, col0, 0, ra, rb, tid);
    stage_slab(sm, ra, rb, tid);
    __syncthreads();

    int cur = 0;
    for (int k0 = 0; k0 < Dm; k0 += 32) {
        const bool has_next = (k0 + 32 < Dm);
        if (has_next) load_slab(A, B, row0, col0, k0 + 32, ra, rb, tid);

        const uint32_t* Wbuf = (const uint32_t*)(sm + cur * BUF_E);
        const uint32_t* Ahw = Wbuf;                 // word stride 20 per row
        const uint32_t* Alw = Wbuf + (ALO >> 1);
        const uint32_t* Bhw = Wbuf + (BHI >> 1);
        const uint32_t* Blw = Wbuf + (BLO >> 1);

        #pragma unroll
        for (int kh = 0; kh < 2; kh++) {
            const int kw = kh * 8 + lc;

            uint32_t ah[2][4], al[2][4];
            #pragma unroll
            for (int mt = 0; mt < 2; mt++) {
                int r = wm + mt * 16 + lr;
                const uint32_t* ph = Ahw + r * 20 + kw;
                const uint32_t* pl = Alw + r * 20 + kw;
                ah[mt][0] = ph[0];      ah[mt][1] = ph[160];
                ah[mt][2] = ph[4];      ah[mt][3] = ph[164];
                al[mt][0] = pl[0];      al[mt][1] = pl[160];
                al[mt][2] = pl[4];      al[mt][3] = pl[164];
            }
            uint32_t bh[4][2], bl[4][2];
            #pragma unroll
            for (int nt = 0; nt < 4; nt++) {
                int n = wn + nt * 8 + lr;
                const uint32_t* ph = Bhw + n * 20 + kw;
                const uint32_t* pl = Blw + n * 20 + kw;
                bh[nt][0] = ph[0];  bh[nt][1] = ph[4];
                bl[nt][0] = pl[0];  bl[nt][1] = pl[4];
            }
            #pragma unroll
            for (int mt = 0; mt < 2; mt++)
                #pragma unroll
                for (int nt = 0; nt < 4; nt++) {
                    mma16(acc[mt][nt], ah[mt], bh[nt]);
                    mma16(acc[mt][nt], al[mt], bh[nt]);
                    mma16(acc[mt][nt], ah[mt], bl[nt]);
                }
        }

        if (has_next) stage_slab(sm + (1 - cur) * BUF_E, ra, rb, tid);
        __syncthreads();
        cur ^= 1;
    }
}

__device__ __forceinline__ void acc_to_smem(float* Cs, const float acc[2][4][4])
{
    const int lane = threadIdx.x & 31;
    const int wid  = threadIdx.x >> 5;
    const int wm   = (wid & 3) * 32;
    const int wn   = (wid >> 2) * 32;
    const int lr = lane >> 2, lc = lane & 3;

    #pragma unroll
    for (int mt = 0; mt < 2; mt++)
        #pragma unroll
        for (int nt = 0; nt < 4; nt++) {
            int r = wm + mt * 16 + lr;
            int n = wn + nt * 8 + 2 * lc;
            #pragma unroll
            for (int i = 0; i < 4; i++)
                Cs[(r + (i >= 2 ? 8 : 0)) * C_STR + n + (i & 1)] = acc[mt][nt][i];
        }
}

// ---------------------------------------------------------------------------
// Kernel 1: fused QKV projection. grid = (T/128, H, 3).
// ---------------------------------------------------------------------------
__global__ void __launch_bounds__(256) qkv_mma_kernel(
    const float* __restrict__ x,
    const float* __restrict__ Wq, const float* __restrict__ bq,
    const float* __restrict__ Wk, const float* __restrict__ bk,
    const float* __restrict__ Wv, const float* __restrict__ bv)
{
    extern __shared__ __nv_bfloat16 smb[];

    const int which = blockIdx.z;
    const float* W = (which == 0) ? Wq : (which == 1) ? Wk : Wv;
    const float* b = (which == 0) ? bq : (which == 1) ? bk : bv;
    float* out = (which == 0) ? g_Qp : (which == 1) ? g_Kp : g_V;

    const int row0 = blockIdx.x * 128;
    const int h    = blockIdx.y;
    const int col0 = h * 64;

    float acc[2][4][4];
    gemm_body(x, W, row0, col0, acc, smb);

    float* Cs = (float*)smb;
    acc_to_smem(Cs, acc);
    __syncthreads();

    const int tid = threadIdx.x;
    #pragma unroll
    for (int it = 0; it < 8; it++) {
        int idx = tid + it * 256;
        int r = idx >> 4, c4 = (idx & 15) << 2;
        float4 v = *(float4*)&Cs[r * C_STR + c4];
        v.x += b[col0 + c4 + 0];
        v.y += b[col0 + c4 + 1];
        v.z += b[col0 + c4 + 2];
        v.w += b[col0 + c4 + 3];
        if (which < 2) {
            v.x = (v.x > 0.f) ? (v.x + 1.f) : expf(v.x);
            v.y = (v.y > 0.f) ? (v.y + 1.f) : expf(v.y);
            v.z = (v.z > 0.f) ? (v.z + 1.f) : expf(v.z);
            v.w = (v.w > 0.f) ? (v.w + 1.f) : expf(v.w);
        }
        *(float4*)&out[((h * T + row0 + r) << 6) + c4] = v;
    }
}

// ---------------------------------------------------------------------------
// Kernel 2: per-(head,chunk) stats: KV = Kp_chunk^T @ V_chunk, ksum.
// ---------------------------------------------------------------------------
__global__ void chunk_kernel()
{
    __shared__ float Ks[32 * 65];
    __shared__ float Vs[32 * 65];

    const int c = blockIdx.x, h = blockIdx.y;
    const int tid = threadIdx.x;
    const int tx = tid & 15, ty = tid >> 4;

    const float* Kbase = g_Kp + ((h * T + c * CH) << 6);
    const float* Vbase = g_V  + ((h * T + c * CH) << 6);

    float acc[4][4];
    #pragma unroll
    for (int i = 0; i < 4; i++)
        #pragma unroll
        for (int j = 0; j < 4; j++) acc[i][j] = 0.f;
    float ks = 0.f;

    for (int sl = 0; sl < 4; sl++) {
        #pragma unroll
        for (int i = 0; i < 8; i++) {
            int idx = tid + i * 256;
            int s = idx >> 6, d = idx & 63;
            Ks[s * 65 + d] = Kbase[((sl * 32 + s) << 6) + d];
            Vs[s * 65 + d] = Vbase[((sl * 32 + s) << 6) + d];
        }
        __syncthreads();
        #pragma unroll
        for (int s = 0; s < 32; s++) {
            float a[4], bb[4];
            #pragma unroll
            for (int i = 0; i < 4; i++) a[i] = Ks[s * 65 + ty * 4 + i];
            #pragma unroll
            for (int j = 0; j < 4; j++) bb[j] = Vs[s * 65 + tx * 4 + j];
            #pragma unroll
            for (int i = 0; i < 4; i++)
                #pragma unroll
                for (int j = 0; j < 4; j++) acc[i][j] += a[i] * bb[j];
        }
        if (tid < 64) {
            #pragma unroll
            for (int s = 0; s < 32; s++) ks += Ks[s * 65 + tid];
        }
        __syncthreads();
    }

    float* outp = g_stats + (h * NC + c) * STATS_STRIDE;
    #pragma unroll
    for (int i = 0; i < 4; i++)
        #pragma unroll
        for (int j = 0; j < 4; j++)
            outp[(ty * 4 + i) * 64 + tx * 4 + j] = acc[i][j];
    if (tid < 64) outp[4096 + tid] = ks;
}

// ---------------------------------------------------------------------------
// Kernel 3: exclusive prefix over chunks — one thread per element.
// grid = (H, 17), 256 threads.
// ---------------------------------------------------------------------------
__global__ void prefix_kernel()
{
    const int h = blockIdx.x;
    const int e = blockIdx.y * 256 + threadIdx.x;
    if (e >= STATS_STRIDE) return;

    float v[NC];
    #pragma unroll
    for (int c = 0; c < NC; c++)
        v[c] = g_stats[(h * NC + c) * STATS_STRIDE + e];

    float run = 0.f;
    #pragma unroll
    for (int c = 0; c < NC; c++) {
        g_pref[(h * NC + c) * STATS_STRIDE + e] = run;
        run += v[c];
    }
}

// ---------------------------------------------------------------------------
// Kernel 4: per-(head,chunk) attention output. float4-vectorized microkernels.
// strides: Q/K/V/Ss = 68, Am = 132 (16B-aligned rows).
// ---------------------------------------------------------------------------
#define QS_STR 68
#define AM_STR 132
#define ATTN_SMEM ((3*128*QS_STR + 64*QS_STR + 64 + 128*AM_STR + 128) * 4)

__global__ void __launch_bounds__(256, 1) attn_kernel()
{
    extern __shared__ float sm[];
    float* Qs   = sm;                          // 128*68
    float* Ks   = Qs + 128 * QS_STR;
    float* Vs   = Ks + 128 * QS_STR;
    float* Ss   = Vs + 128 * QS_STR;           // 64*68
    float* zs   = Ss + 64 * QS_STR;            // 64
    float* Am   = zs + 64;                     // 128*132
    float* dens = Am + 128 * AM_STR;           // 128

    const int c = blockIdx.x, h = blockIdx.y;
    const int tid = threadIdx.x;

    const float* Qbase = g_Qp + ((h * T + c * CH) << 6);
    const float* Kbase = g_Kp + ((h * T + c * CH) << 6);
    const float* Vbase = g_V  + ((h * T + c * CH) << 6);
    const float* P     = g_pref + (h * NC + c) * STATS_STRIDE;

    #pragma unroll
    for (int i = 0; i < 8; i++) {              // 2048 float4 per array
        int slot = tid + i * 256;
        int t = slot >> 4, c4 = (slot & 15) << 2;
        *(float4*)&Qs[t * QS_STR + c4] = *(const float4*)&Qbase[(t << 6) + c4];
        *(float4*)&Ks[t * QS_STR + c4] = *(const float4*)&Kbase[(t << 6) + c4];
        *(float4*)&Vs[t * QS_STR + c4] = *(const float4*)&Vbase[(t << 6) + c4];
    }
    #pragma unroll
    for (int i = 0; i < 4; i++) {              // Sprev 1024 float4
        int slot = tid + i * 256;
        int r = slot >> 4, c4 = (slot & 15) << 2;
        *(float4*)&Ss[r * QS_STR + c4] = *(const float4*)&P[(r << 6) + c4];
    }
    if (tid < 64) zs[tid] = P[4096 + tid];
    __syncthreads();

    const int ti = tid >> 4, tj = tid & 15;

    // Phase A: A[t][s] = (s<=t) ? Qp[t].Kp[s] : 0, float4 over k.
    {
        float a[8][8];
        #pragma unroll
        for (int i = 0; i < 8; i++)
            #pragma unroll
            for (int j = 0; j < 8; j++) a[i][j] = 0.f;

        for (int k4 = 0; k4 < 16; k4++) {
            float4 q4[8];
            #pragma unroll
            for (int i = 0; i < 8; i++)
                q4[i] = *(const float4*)&Qs[(ti * 8 + i) * QS_STR + k4 * 4];
            #pragma unroll
            for (int j = 0; j < 8; j++) {
                float4 kb = *(const float4*)&Ks[(tj * 8 + j) * QS_STR + k4 * 4];
                #pragma unroll
                for (int i = 0; i < 8; i++)
                    a[i][j] += q4[i].x * kb.x + q4[i].y * kb.y
                             + q4[i].z * kb.z + q4[i].w * kb.w;
            }
        }
        #pragma unroll
        for (int i = 0; i < 8; i++) {
            int t = ti * 8 + i;
            #pragma unroll
            for (int j = 0; j < 8; j++) {
                int s = tj * 8 + j;
                Am[t * AM_STR + s] = (s <= t) ? a[i][j] : 0.f;
            }
        }
    }
    __syncthreads();

    if (tid < 128) {
        int t = tid;
        float d = 0.f;
        #pragma unroll
        for (int i4 = 0; i4 < 16; i4++) {
            float4 q = *(const float4*)&Qs[t * QS_STR + i4 * 4];
            float4 z = *(const float4*)&zs[i4 * 4];
            d += q.x * z.x + q.y * z.y + q.z * z.z + q.w * z.w;
        }
        #pragma unroll
        for (int s4 = 0; s4 < 32; s4++) {
            float4 av = *(const float4*)&Am[t * AM_STR + s4 * 4];
            d += av.x + av.y + av.z + av.w;
        }
        dens[t] = fmaxf(d, 1e-6f);
    }
    __syncthreads();

    // Phase B: out = Qp@Sprev + A@V, float4 over the k dims.
    {
        float acc[8][4];
        #pragma unroll
        for (int r = 0; r < 8; r++)
            #pragma unroll
            for (int j = 0; j < 4; j++) acc[r][j] = 0.f;

        for (int i4 = 0; i4 < 16; i4++) {       // inter: k = feature (64)
            float4 s0 = *(const float4*)&Ss[(i4*4+0) * QS_STR + tj * 4];
            float4 s1 = *(const float4*)&Ss[(i4*4+1) * QS_STR + tj * 4];
            float4 s2 = *(const float4*)&Ss[(i4*4+2) * QS_STR + tj * 4];
            float4 s3 = *(const float4*)&Ss[(i4*4+3) * QS_STR + tj * 4];
            #pragma unroll
            for (int r = 0; r < 8; r++) {
                float4 q = *(const float4*)&Qs[(ti * 8 + r) * QS_STR + i4 * 4];
                acc[r][0] += q.x*s0.x + q.y*s1.x + q.z*s2.x + q.w*s3.x;
                acc[r][1] += q.x*s0.y + q.y*s1.y + q.z*s2.y + q.w*s3.y;
                acc[r][2] += q.x*s0.z + q.y*s1.z + q.z*s2.z + q.w*s3.z;
                acc[r][3] += q.x*s0.w + q.y*s1.w + q.z*s2.w + q.w*s3.w;
            }
        }
        for (int s4 = 0; s4 < 32; s4++) {       // intra: k = s (128)
            float4 v0 = *(const float4*)&Vs[(s4*4+0) * QS_STR + tj * 4];
            float4 v1 = *(const float4*)&Vs[(s4*4+1) * QS_STR + tj * 4];
            float4 v2 = *(const float4*)&Vs[(s4*4+2) * QS_STR + tj * 4];
            float4 v3 = *(const float4*)&Vs[(s4*4+3) * QS_STR + tj * 4];
            #pragma unroll
            for (int r = 0; r < 8; r++) {
                float4 av = *(const float4*)&Am[(ti * 8 + r) * AM_STR + s4 * 4];
                acc[r][0] += av.x*v0.x + av.y*v1.x + av.z*v2.x + av.w*v3.x;
                acc[r][1] += av.x*v0.y + av.y*v1.y + av.z*v2.y + av.w*v3.y;
                acc[r][2] += av.x*v0.z + av.y*v1.z + av.z*v2.z + av.w*v3.z;
                acc[r][3] += av.x*v0.w + av.y*v1.w + av.z*v2.w + av.w*v3.w;
            }
        }

        float* Ob = g_O + (c * CH) * Dm + h * DH;
        #pragma unroll
        for (int r = 0; r < 8; r++) {
            int t = ti * 8 + r;
            float inv = 1.f / dens[t];
            #pragma unroll
            for (int j = 0; j < 4; j++)
                Ob[t * Dm + tj * 4 + j] = acc[r][j] * inv;
        }
    }
}

// ---------------------------------------------------------------------------
// Kernel 5: output projection.  grid = (T/128, Dm/64)
// ---------------------------------------------------------------------------
__global__ void __launch_bounds__(256) out_mma_kernel(
    const float* __restrict__ Wo,
    const float* __restrict__ bo,
    float* __restrict__ y)
{
    extern __shared__ __nv_bfloat16 smb[];

    const int row0 = blockIdx.x * 128;
    const int col0 = blockIdx.y * 64;

    float acc[2][4][4];
    gemm_body(g_O, Wo, row0, col0, acc, smb);

    float* Cs = (float*)smb;
    acc_to_smem(Cs, acc);
    __syncthreads();

    const int tid = threadIdx.x;
    #pragma unroll
    for (int it = 0; it < 8; it++) {
        int idx = tid + it * 256;
        int r = idx >> 4, c4 = (idx & 15) << 2;
        float4 v = *(float4*)&Cs[r * C_STR + c4];
        v.x += bo[col0 + c4 + 0];
        v.y += bo[col0 + c4 + 1];
        v.z += bo[col0 + c4 + 2];
        v.w += bo[col0 + c4 + 3];
        *(float4*)&y[(row0 + r) * Dm + col0 + c4] = v;
    }
}

// ---------------------------------------------------------------------------
extern "C" void kernel_launch(void* const* d_in, const int* in_sizes, int n_in,
                              void* d_out, int out_size)
{
    const float* x  = (const float*)d_in[0];
    const float* Wq = (const float*)d_in[1];
    const float* bq = (const float*)d_in[2];
    const float* Wk = (const float*)d_in[3];
    const float* bk = (const float*)d_in[4];
    const float* Wv = (const float*)d_in[5];
    const float* bv = (const float*)d_in[6];
    const float* Wo = (const float*)d_in[7];
    const float* bo = (const float*)d_in[8];
    float* y = (float*)d_out;

    cudaFuncSetAttribute(attn_kernel,
                         cudaFuncAttributeMaxDynamicSharedMemorySize, ATTN_SMEM);
    cudaFuncSetAttribute(qkv_mma_kernel,
                         cudaFuncAttributeMaxDynamicSharedMemorySize, GEMM_SMEM);
    cudaFuncSetAttribute(out_mma_kernel,
                         cudaFuncAttributeMaxDynamicSharedMemorySize, GEMM_SMEM);

    qkv_mma_kernel<<<dim3(T/128, H, 3), 256, GEMM_SMEM>>>(x, Wq, bq, Wk, bk, Wv, bv);
    chunk_kernel  <<<dim3(NC, H), 256>>>();
    prefix_kernel <<<dim3(H, (STATS_STRIDE + 255) / 256), 256>>>();
    attn_kernel   <<<dim3(NC, H), 256, ATTN_SMEM>>>();
    out_mma_kernel<<<dim3(T/128, Dm/64), 256, GEMM_SMEM>>>(Wo, bo, y);
}

// round 5
// speedup vs baseline: 2.0529x; 1.2486x over previous
#include <cuda_runtime.h>
#include <cuda_bf16.h>
#include <math.h>
#include <stdint.h>

// Problem constants
#define T   2048
#define Dm  512
#define H   8
#define DH  64
#define CH  128
#define NC  (T / CH)
#define STATS_STRIDE (DH*DH + DH)   // 4160

// Scratch (device globals — no allocation allowed)
__device__ float g_Qp[H * T * DH];
__device__ float g_Kp[H * T * DH];
__device__ float g_V [H * T * DH];
__device__ float g_stats[H * NC * STATS_STRIDE];  // [i*64+j] KV + ksum @4096
__device__ float g_pref [H * NC * STATS_STRIDE];  // TRANSPOSED: [j*64+i] + ksum @4096
__device__ float g_O [T * Dm];

// ===========================================================================
// Shared bf16-split helpers
// ===========================================================================
__device__ __forceinline__ uint32_t pack_bf2(float a, float b) {
    __nv_bfloat162 t;
    t.x = __float2bfloat16_rn(a);
    t.y = __float2bfloat16_rn(b);
    return *(uint32_t*)&t;
}
__device__ __forceinline__ float bfr(float x) {
    return __bfloat162float(__float2bfloat16_rn(x));
}
__device__ __forceinline__ void mma16(float c[4], const uint32_t a[4], const uint32_t b[2]) {
    asm volatile(
        "mma.sync.aligned.m16n8k16.row.col.f32.bf16.bf16.f32 "
        "{%0,%1,%2,%3}, {%4,%5,%6,%7}, {%8,%9}, {%0,%1,%2,%3};"
        : "+f"(c[0]), "+f"(c[1]), "+f"(c[2]), "+f"(c[3])
        : "r"(a[0]), "r"(a[1]), "r"(a[2]), "r"(a[3]),
          "r"(b[0]), "r"(b[1]));
}

// Row-major split staging: src [rows][64] fp32 -> dst split bf16, 36 words/row
__device__ __forceinline__ void stage_rowmajor(uint32_t* smw, int offH, int offL,
                                               const float* __restrict__ src,
                                               int rows, int tid)
{
    int iters = rows >> 4;             // rows*16 slots / 256 threads
    for (int i = 0; i < iters; i++) {
        int slot = tid + i * 256;
        int r = slot >> 4, c4 = (slot & 15) << 2;
        float4 v = *(const float4*)&src[(r << 6) + c4];
        float h0 = bfr(v.x), h1 = bfr(v.y), h2 = bfr(v.z), h3 = bfr(v.w);
        int w = r * 36 + (c4 >> 1);
        *(uint2*)(smw + offH + w) = make_uint2(pack_bf2(h0, h1), pack_bf2(h2, h3));
        *(uint2*)(smw + offL + w) = make_uint2(pack_bf2(v.x - h0, v.y - h1),
                                               pack_bf2(v.z - h2, v.w - h3));
    }
}

// Transposed split staging: src [128][64] fp32 (t-major) -> dst [64 rows d][68 words],
// words along t (bf16 pairs), XOR-swizzled: word = t2 ^ ((d>>3)&3). Returns column sum.
__device__ __forceinline__ float stage_transposed(uint32_t* smw, int offH, int offL,
                                                  const float* __restrict__ src, int tid)
{
    int d = tid & 63, tb = tid >> 6;
    int sw = (d >> 3) & 3;
    const float* col = src + d;
    uint32_t* ph = smw + offH + d * 68;
    uint32_t* pl = smw + offL + d * 68;
    float s = 0.f;
    #pragma unroll
    for (int u2 = 0; u2 < 16; u2++) {
        int t = tb * 32 + u2 * 2;
        float v0 = col[t << 6];
        float v1 = col[(t + 1) << 6];
        s += v0 + v1;
        float h0 = bfr(v0), h1 = bfr(v1);
        int w = (tb * 16 + u2) ^ sw;
        ph[w] = pack_bf2(h0, h1);
        pl[w] = pack_bf2(v0 - h0, v1 - h1);
    }
    return s;   // partial sum of this thread's 32 column elements
}

// ===========================================================================
// GEMM machinery (unchanged from R4): bf16 split, BM=128 BN=64 BK=32
// ===========================================================================
#define A_STR 40
#define AHI 0
#define ALO (128 * A_STR)
#define BHI (2 * 128 * A_STR)
#define BLO (BHI + 64 * A_STR)
#define BUF_E (BHI + 2 * 64 * A_STR)
#define GEMM_SMEM (2 * BUF_E * (int)sizeof(__nv_bfloat16))
#define C_STR 68

__device__ __forceinline__ void load_slab(const float* __restrict__ A,
                                          const float* __restrict__ B,
                                          int row0, int col0, int k0,
                                          float4 ra[4], float4 rb[2], int tid)
{
    #pragma unroll
    for (int i = 0; i < 4; i++) {
        int slot = tid + i * 256;
        int r = slot >> 3, c4 = (slot & 7) << 2;
        ra[i] = *(const float4*)&A[(row0 + r) * Dm + k0 + c4];
    }
    #pragma unroll
    for (int i = 0; i < 2; i++) {
        int slot = tid + i * 256;
        int r = slot >> 4, c4 = (slot & 15) << 2;
        rb[i] = *(const float4*)&B[(k0 + r) * Dm + col0 + c4];
    }
}

__device__ __forceinline__ void stage_slab(__nv_bfloat16* __restrict__ buf,
                                           const float4 ra[4], const float4 rb[2],
                                           int tid)
{
    #pragma unroll
    for (int i = 0; i < 4; i++) {
        int slot = tid + i * 256;
        int r = slot >> 3, c4 = (slot & 7) << 2;
        float x0 = ra[i].x, x1 = ra[i].y, x2 = ra[i].z, x3 = ra[i].w;
        float h0 = bfr(x0), h1 = bfr(x1), h2 = bfr(x2), h3 = bfr(x3);
        *(uint2*)&buf[AHI + r * A_STR + c4] = make_uint2(pack_bf2(h0, h1), pack_bf2(h2, h3));
        *(uint2*)&buf[ALO + r * A_STR + c4] = make_uint2(pack_bf2(x0 - h0, x1 - h1),
                                                         pack_bf2(x2 - h2, x3 - h3));
    }
    #pragma unroll
    for (int i = 0; i < 2; i++) {
        int slot = tid + i * 256;
        int r = slot >> 4, c4 = (slot & 15) << 2;
        float x[4] = {rb[i].x, rb[i].y, rb[i].z, rb[i].w};
        #pragma unroll
        for (int j = 0; j < 4; j++) {
            __nv_bfloat16 hb = __float2bfloat16_rn(x[j]);
            float hf = __bfloat162float(hb);
            buf[BHI + (c4 + j) * A_STR + r] = hb;
            buf[BLO + (c4 + j) * A_STR + r] = __float2bfloat16_rn(x[j] - hf);
        }
    }
}

__device__ __forceinline__ void gemm_body(const float* __restrict__ A,
                                          const float* __restrict__ B,
                                          int row0, int col0,
                                          float acc[2][4][4],
                                          __nv_bfloat16* sm)
{
    const int tid  = threadIdx.x;
    const int lane = tid & 31;
    const int wid  = tid >> 5;
    const int wm   = (wid & 3) * 32;
    const int wn   = (wid >> 2) * 32;
    const int lr   = lane >> 2;
    const int lc   = lane & 3;

    #pragma unroll
    for (int mt = 0; mt < 2; mt++)
        #pragma unroll
        for (int nt = 0; nt < 4; nt++)
            #pragma unroll
            for (int i = 0; i < 4; i++) acc[mt][nt][i] = 0.f;

    float4 ra[4]; float4 rb[2];
    load_slab(A, B, row0, col0, 0, ra, rb, tid);
    stage_slab(sm, ra, rb, tid);
    __syncthreads();

    int cur = 0;
    for (int k0 = 0; k0 < Dm; k0 += 32) {
        const bool has_next = (k0 + 32 < Dm);
        if (has_next) load_slab(A, B, row0, col0, k0 + 32, ra, rb, tid);

        const uint32_t* Wbuf = (const uint32_t*)(sm + cur * BUF_E);
        const uint32_t* Ahw = Wbuf;
        const uint32_t* Alw = Wbuf + (ALO >> 1);
        const uint32_t* Bhw = Wbuf + (BHI >> 1);
        const uint32_t* Blw = Wbuf + (BLO >> 1);

        #pragma unroll
        for (int kh = 0; kh < 2; kh++) {
            const int kw = kh * 8 + lc;

            uint32_t ah[2][4], al[2][4];
            #pragma unroll
            for (int mt = 0; mt < 2; mt++) {
                int r = wm + mt * 16 + lr;
                const uint32_t* ph = Ahw + r * 20 + kw;
                const uint32_t* pl = Alw + r * 20 + kw;
                ah[mt][0] = ph[0];      ah[mt][1] = ph[160];
                ah[mt][2] = ph[4];      ah[mt][3] = ph[164];
                al[mt][0] = pl[0];      al[mt][1] = pl[160];
                al[mt][2] = pl[4];      al[mt][3] = pl[164];
            }
            uint32_t bh[4][2], bl[4][2];
            #pragma unroll
            for (int nt = 0; nt < 4; nt++) {
                int n = wn + nt * 8 + lr;
                const uint32_t* ph = Bhw + n * 20 + kw;
                const uint32_t* pl = Blw + n * 20 + kw;
                bh[nt][0] = ph[0];  bh[nt][1] = ph[4];
                bl[nt][0] = pl[0];  bl[nt][1] = pl[4];
            }
            #pragma unroll
            for (int mt = 0; mt < 2; mt++)
                #pragma unroll
                for (int nt = 0; nt < 4; nt++) {
                    mma16(acc[mt][nt], ah[mt], bh[nt]);
                    mma16(acc[mt][nt], al[mt], bh[nt]);
                    mma16(acc[mt][nt], ah[mt], bl[nt]);
                }
        }

        if (has_next) stage_slab(sm + (1 - cur) * BUF_E, ra, rb, tid);
        __syncthreads();
        cur ^= 1;
    }
}

__device__ __forceinline__ void acc_to_smem(float* Cs, const float acc[2][4][4])
{
    const int lane = threadIdx.x & 31;
    const int wid  = threadIdx.x >> 5;
    const int wm   = (wid & 3) * 32;
    const int wn   = (wid >> 2) * 32;
    const int lr = lane >> 2, lc = lane & 3;

    #pragma unroll
    for (int mt = 0; mt < 2; mt++)
        #pragma unroll
        for (int nt = 0; nt < 4; nt++) {
            int r = wm + mt * 16 + lr;
            int n = wn + nt * 8 + 2 * lc;
            #pragma unroll
            for (int i = 0; i < 4; i++)
                Cs[(r + (i >= 2 ? 8 : 0)) * C_STR + n + (i & 1)] = acc[mt][nt][i];
        }
}

// ---------------------------------------------------------------------------
// Kernel 1: fused QKV projection. grid = (T/128, H, 3).
// ---------------------------------------------------------------------------
__global__ void __launch_bounds__(256) qkv_mma_kernel(
    const float* __restrict__ x,
    const float* __restrict__ Wq, const float* __restrict__ bq,
    const float* __restrict__ Wk, const float* __restrict__ bk,
    const float* __restrict__ Wv, const float* __restrict__ bv)
{
    extern __shared__ __nv_bfloat16 smb[];

    const int which = blockIdx.z;
    const float* W = (which == 0) ? Wq : (which == 1) ? Wk : Wv;
    const float* b = (which == 0) ? bq : (which == 1) ? bk : bv;
    float* out = (which == 0) ? g_Qp : (which == 1) ? g_Kp : g_V;

    const int row0 = blockIdx.x * 128;
    const int h    = blockIdx.y;
    const int col0 = h * 64;

    float acc[2][4][4];
    gemm_body(x, W, row0, col0, acc, smb);

    float* Cs = (float*)smb;
    acc_to_smem(Cs, acc);
    __syncthreads();

    const int tid = threadIdx.x;
    #pragma unroll
    for (int it = 0; it < 8; it++) {
        int idx = tid + it * 256;
        int r = idx >> 4, c4 = (idx & 15) << 2;
        float4 v = *(float4*)&Cs[r * C_STR + c4];
        v.x += b[col0 + c4 + 0];
        v.y += b[col0 + c4 + 1];
        v.z += b[col0 + c4 + 2];
        v.w += b[col0 + c4 + 3];
        if (which < 2) {
            v.x = (v.x > 0.f) ? (v.x + 1.f) : expf(v.x);
            v.y = (v.y > 0.f) ? (v.y + 1.f) : expf(v.y);
            v.z = (v.z > 0.f) ? (v.z + 1.f) : expf(v.z);
            v.w = (v.w > 0.f) ? (v.w + 1.f) : expf(v.w);
        }
        *(float4*)&out[((h * T + row0 + r) << 6) + c4] = v;
    }
}

// ===========================================================================
// Kernel 2: chunk stats via tensor cores.
// KV[i][j] = sum_s Kp[s][i]*V[s][j] (64x64x128), ksum[i] = sum_s Kp[s][i].
// Kt and Vt staged transposed (swizzled split bf16). 8 warps: (wid&3)->16 rows,
// (wid>>2)->32-col half. grid = (NC, H).
// ===========================================================================
#define CK_KH 0
#define CK_KL (64*68)
#define CK_VH (2*64*68)
#define CK_VL (3*64*68)
#define CK_PART (4*64*68)
#define CHUNK_SMEM ((CK_PART + 256) * 4)   // 70656 B

__global__ void __launch_bounds__(256, 1) chunk_mma_kernel()
{
    extern __shared__ uint32_t smw[];
    float* kpart = (float*)(smw + CK_PART);

    const int c = blockIdx.x, h = blockIdx.y;
    const int tid = threadIdx.x;
    const float* Kbase = g_Kp + ((h * T + c * CH) << 6);
    const float* Vbase = g_V  + ((h * T + c * CH) << 6);

    float ks = stage_transposed(smw, CK_KH, CK_KL, Kbase, tid);
    kpart[(tid >> 6) * 64 + (tid & 63)] = ks;
    stage_transposed(smw, CK_VH, CK_VL, Vbase, tid);
    __syncthreads();

    const int lane = tid & 31, wid = tid >> 5;
    const int lr = lane >> 2, lc = lane & 3;
    const int wm = (wid & 3) * 16;
    const int wn = (wid >> 2) * 32;
    const int i0 = wm + lr, i1 = i0 + 8;

    // a-frags from Kt (row-dependent swizzle)
    uint32_t ah[8][4], al[8][4];
    {
        const int sw0 = (i0 >> 3) & 3;
        const int sw1 = (i1 >> 3) & 3;
        const uint32_t* h0 = smw + CK_KH + i0 * 68;
        const uint32_t* h1 = smw + CK_KH + i1 * 68;
        const uint32_t* l0 = smw + CK_KL + i0 * 68;
        const uint32_t* l1 = smw + CK_KL + i1 * 68;
        #pragma unroll
        for (int kh = 0; kh < 8; kh++) {
            int w0 = (kh * 8 + lc) ^ sw0;
            int w1 = (kh * 8 + lc) ^ sw1;
            ah[kh][0] = h0[w0];     ah[kh][1] = h1[w1];
            ah[kh][2] = h0[w0 + 4]; ah[kh][3] = h1[w1 + 4];
            al[kh][0] = l0[w0];     al[kh][1] = l1[w1];
            al[kh][2] = l0[w0 + 4]; al[kh][3] = l1[w1 + 4];
        }
    }

    float cb[4][4];
    #pragma unroll
    for (int nt = 0; nt < 4; nt++)
        #pragma unroll
        for (int i = 0; i < 4; i++) cb[nt][i] = 0.f;

    #pragma unroll
    for (int nt = 0; nt < 4; nt++) {
        int n = wn + nt * 8 + lr;
        int swB = (n >> 3) & 3;
        const uint32_t* vh = smw + CK_VH + n * 68;
        const uint32_t* vl = smw + CK_VL + n * 68;
        #pragma unroll
        for (int kh = 0; kh < 8; kh++) {
            int w = (kh * 8 + lc) ^ swB;
            uint32_t bh[2] = {vh[w], vh[w + 4]};
            uint32_t bl[2] = {vl[w], vl[w + 4]};
            mma16(cb[nt], ah[kh], bh);
            mma16(cb[nt], al[kh], bh);
            mma16(cb[nt], ah[kh], bl);
        }
    }

    float* outp = g_stats + (h * NC + c) * STATS_STRIDE;
    #pragma unroll
    for (int nt = 0; nt < 4; nt++) {
        int j0 = wn + nt * 8 + 2 * lc;
        *(float2*)&outp[i0 * 64 + j0] = make_float2(cb[nt][0], cb[nt][1]);
        *(float2*)&outp[i1 * 64 + j0] = make_float2(cb[nt][2], cb[nt][3]);
    }
    if (tid < 64)
        outp[4096 + tid] = kpart[tid] + kpart[64 + tid] + kpart[128 + tid] + kpart[192 + tid];
}

// ---------------------------------------------------------------------------
// Kernel 3: exclusive prefix over chunks, TRANSPOSED output for KV part.
// g_pref[...][j*64+i] = excl-cumsum_c g_stats[...][i*64+j]; ksum passthrough.
// grid = (H, 17), 256 threads.
// ---------------------------------------------------------------------------
__global__ void prefix_kernel()
{
    const int hh = blockIdx.x;
    const int e = blockIdx.y * 256 + threadIdx.x;
    if (e >= STATS_STRIDE) return;

    int src_e;
    if (e < 4096) {
        int j = e >> 6, i = e & 63;
        src_e = i * 64 + j;
    } else {
        src_e = e;
    }

    float v[NC];
    #pragma unroll
    for (int c = 0; c < NC; c++)
        v[c] = g_stats[(hh * NC + c) * STATS_STRIDE + src_e];

    float run = 0.f;
    #pragma unroll
    for (int c = 0; c < NC; c++) {
        g_pref[(hh * NC + c) * STATS_STRIDE + e] = run;
        run += v[c];
    }
}

// ===========================================================================
// Kernel 4: attention via tensor cores.
// Phase A: A = mask(Qp Kp^T) (128x128x64) + per-row sums (denominator intra part).
// Phase B: O_num = A V + Qp Sprev (K-concat), den inter part folded in as a
//          9th n-tile of St whose row 64 holds z (ksum prefix).
// grid = (NC, H), 256 threads, ~194 KB smem.
// ===========================================================================
#define OFF_QH 0
#define OFF_QL (OFF_QH + 128*36)
#define OFF_KH (OFF_QL + 128*36)
#define OFF_KL (OFF_KH + 128*36)
#define OFF_VH (OFF_KL + 128*36)
#define OFF_VL (OFF_VH + 64*68)
#define OFF_SH (OFF_VL + 64*68)
#define OFF_SL (OFF_SH + 72*36)
#define OFF_AH (OFF_SL + 72*36)
#define OFF_AL (OFF_AH + 128*68)
#define ATTN_SMEM ((OFF_AL + 128*68) * 4)   // 198912 B

__global__ void __launch_bounds__(256, 1) attn_kernel()
{
    extern __shared__ uint32_t smw[];

    const int c = blockIdx.x, h = blockIdx.y;
    const int tid = threadIdx.x;
    const float* Qbase = g_Qp + ((h * T + c * CH) << 6);
    const float* Kbase = g_Kp + ((h * T + c * CH) << 6);
    const float* Vbase = g_V  + ((h * T + c * CH) << 6);
    const float* P     = g_pref + (h * NC + c) * STATS_STRIDE;

    stage_rowmajor(smw, OFF_QH, OFF_QL, Qbase, 128, tid);
    stage_rowmajor(smw, OFF_KH, OFF_KL, Kbase, 128, tid);
    stage_rowmajor(smw, OFF_SH, OFF_SL, P, 64, tid);      // St rows 0..63 (transposed S)
    stage_transposed(smw, OFF_VH, OFF_VL, Vbase, tid);
    // St rows 64..71: row 64 = z (ksum prefix), rows 65..71 = 0
    if (tid < 128) {
        int r = 64 + (tid >> 4), c4 = (tid & 15) << 2;
        float4 v = make_float4(0.f, 0.f, 0.f, 0.f);
        if (r == 64) v = *(const float4*)&P[4096 + c4];
        float h0 = bfr(v.x), h1 = bfr(v.y), h2 = bfr(v.z), h3 = bfr(v.w);
        int w = r * 36 + (c4 >> 1);
        *(uint2*)(smw + OFF_SH + w) = make_uint2(pack_bf2(h0, h1), pack_bf2(h2, h3));
        *(uint2*)(smw + OFF_SL + w) = make_uint2(pack_bf2(v.x - h0, v.y - h1),
                                                 pack_bf2(v.z - h2, v.w - h3));
    }
    __syncthreads();

    const int lane = tid & 31, wid = tid >> 5;
    const int lr = lane >> 2, lc = lane & 3;
    const int wm = wid * 16;
    const int t0 = wm + lr, t1 = t0 + 8;

    // Q a-frags (shared by phase A and phase B)
    uint32_t qh[4][4], ql[4][4];
    {
        const uint32_t* ph = smw + OFF_QH + t0 * 36 + lc;
        const uint32_t* pl = smw + OFF_QL + t0 * 36 + lc;
        #pragma unroll
        for (int kh = 0; kh < 4; kh++) {
            int o = kh * 8;
            qh[kh][0] = ph[o];     qh[kh][1] = ph[o + 288];
            qh[kh][2] = ph[o + 4]; qh[kh][3] = ph[o + 292];
            ql[kh][0] = pl[o];     ql[kh][1] = pl[o + 288];
            ql[kh][2] = pl[o + 4]; ql[kh][3] = pl[o + 292];
        }
    }

    // ---- Phase A: A = Qp Kp^T (warp: 16 rows x 128 cols) ----
    float ca[16][4];
    #pragma unroll
    for (int nt = 0; nt < 16; nt++)
        #pragma unroll
        for (int i = 0; i < 4; i++) ca[nt][i] = 0.f;

    #pragma unroll
    for (int nt = 0; nt < 16; nt++) {
        const uint32_t* bhp = smw + OFF_KH + (nt * 8 + lr) * 36 + lc;
        const uint32_t* blp = smw + OFF_KL + (nt * 8 + lr) * 36 + lc;
        #pragma unroll
        for (int kh = 0; kh < 4; kh++) {
            uint32_t bh[2] = {bhp[kh * 8], bhp[kh * 8 + 4]};
            uint32_t bl[2] = {blp[kh * 8], blp[kh * 8 + 4]};
            mma16(ca[nt], qh[kh], bh);
            mma16(ca[nt], ql[kh], bh);
            mma16(ca[nt], qh[kh], bl);
        }
    }

    // mask + rowsum + split-store A
    float rs0 = 0.f, rs1 = 0.f;
    #pragma unroll
    for (int nt = 0; nt < 16; nt++) {
        int s0 = nt * 8 + 2 * lc;
        float c0 = (s0     <= t0) ? ca[nt][0] : 0.f;
        float c1 = (s0 + 1 <= t0) ? ca[nt][1] : 0.f;
        float c2 = (s0     <= t1) ? ca[nt][2] : 0.f;
        float c3 = (s0 + 1 <= t1) ? ca[nt][3] : 0.f;
        rs0 += c0 + c1;
        rs1 += c2 + c3;
        float h0 = bfr(c0), h1 = bfr(c1), h2 = bfr(c2), h3 = bfr(c3);
        int w = nt * 4 + lc;
        smw[OFF_AH + t0 * 68 + w] = pack_bf2(h0, h1);
        smw[OFF_AL + t0 * 68 + w] = pack_bf2(c0 - h0, c1 - h1);
        smw[OFF_AH + t1 * 68 + w] = pack_bf2(h2, h3);
        smw[OFF_AL + t1 * 68 + w] = pack_bf2(c2 - h2, c3 - h3);
    }
    rs0 += __shfl_xor_sync(0xffffffffu, rs0, 1);
    rs0 += __shfl_xor_sync(0xffffffffu, rs0, 2);
    rs1 += __shfl_xor_sync(0xffffffffu, rs1, 1);
    rs1 += __shfl_xor_sync(0xffffffffu, rs1, 2);
    __syncthreads();

    // ---- Phase B: O_num = A V + Qp St^T  (warp: 16 rows x 64 cols + den tile) ----
    uint32_t aAh[8][4], aAl[8][4];
    {
        const uint32_t* ph = smw + OFF_AH + t0 * 68 + lc;
        const uint32_t* pl = smw + OFF_AL + t0 * 68 + lc;
        #pragma unroll
        for (int kh = 0; kh < 8; kh++) {
            int o = kh * 8;
            aAh[kh][0] = ph[o];     aAh[kh][1] = ph[o + 544];
            aAh[kh][2] = ph[o + 4]; aAh[kh][3] = ph[o + 548];
            aAl[kh][0] = pl[o];     aAl[kh][1] = pl[o + 544];
            aAl[kh][2] = pl[o + 4]; aAl[kh][3] = pl[o + 548];
        }
    }

    float cb[9][4];
    #pragma unroll
    for (int nt = 0; nt < 9; nt++)
        #pragma unroll
        for (int i = 0; i < 4; i++) cb[nt][i] = 0.f;

    #pragma unroll
    for (int nt = 0; nt < 8; nt++) {
        int n = nt * 8 + lr;
        int swB = nt & 3;                    // (n>>3)&3 with lr<8
        const uint32_t* vh = smw + OFF_VH + n * 68;
        const uint32_t* vl = smw + OFF_VL + n * 68;
        #pragma unroll
        for (int kh = 0; kh < 8; kh++) {
            int w = (kh * 8 + lc) ^ swB;
            uint32_t bh[2] = {vh[w], vh[w + 4]};
            uint32_t bl[2] = {vl[w], vl[w + 4]};
            mma16(cb[nt], aAh[kh], bh);
            mma16(cb[nt], aAl[kh], bh);
            mma16(cb[nt], aAh[kh], bl);
        }
        const uint32_t* sh = smw + OFF_SH + n * 36 + lc;
        const uint32_t* sl = smw + OFF_SL + n * 36 + lc;
        #pragma unroll
        for (int ks = 0; ks < 4; ks++) {
            uint32_t bh[2] = {sh[ks * 8], sh[ks * 8 + 4]};
            uint32_t bl[2] = {sl[ks * 8], sl[ks * 8 + 4]};
            mma16(cb[nt], qh[ks], bh);
            mma16(cb[nt], ql[ks], bh);
            mma16(cb[nt], qh[ks], bl);
        }
    }
    // den tile: St rows 64..71 (row 64 = z)
    {
        int n = 64 + lr;
        const uint32_t* sh = smw + OFF_SH + n * 36 + lc;
        const uint32_t* sl = smw + OFF_SL + n * 36 + lc;
        #pragma unroll
        for (int ks = 0; ks < 4; ks++) {
            uint32_t bh[2] = {sh[ks * 8], sh[ks * 8 + 4]};
            uint32_t bl[2] = {sl[ks * 8], sl[ks * 8 + 4]};
            mma16(cb[8], qh[ks], bh);
            mma16(cb[8], ql[ks], bh);
            mma16(cb[8], qh[ks], bl);
        }
    }

    // denominator: rs + Qp.z (cb[8][0]/[2] on lanes with lc==0, col 64)
    float di0 = __shfl_sync(0xffffffffu, cb[8][0], lane & ~3);
    float di1 = __shfl_sync(0xffffffffu, cb[8][2], lane & ~3);
    float inv0 = 1.f / fmaxf(rs0 + di0, 1e-6f);
    float inv1 = 1.f / fmaxf(rs1 + di1, 1e-6f);

    float* Ob = g_O + (c * CH) * Dm + h * 64;
    #pragma unroll
    for (int nt = 0; nt < 8; nt++) {
        int j = nt * 8 + 2 * lc;
        *(float2*)&Ob[t0 * Dm + j] = make_float2(cb[nt][0] * inv0, cb[nt][1] * inv0);
        *(float2*)&Ob[t1 * Dm + j] = make_float2(cb[nt][2] * inv1, cb[nt][3] * inv1);
    }
}

// ---------------------------------------------------------------------------
// Kernel 5: output projection.  grid = (T/128, Dm/64)
// ---------------------------------------------------------------------------
__global__ void __launch_bounds__(256) out_mma_kernel(
    const float* __restrict__ Wo,
    const float* __restrict__ bo,
    float* __restrict__ y)
{
    extern __shared__ __nv_bfloat16 smb[];

    const int row0 = blockIdx.x * 128;
    const int col0 = blockIdx.y * 64;

    float acc[2][4][4];
    gemm_body(g_O, Wo, row0, col0, acc, smb);

    float* Cs = (float*)smb;
    acc_to_smem(Cs, acc);
    __syncthreads();

    const int tid = threadIdx.x;
    #pragma unroll
    for (int it = 0; it < 8; it++) {
        int idx = tid + it * 256;
        int r = idx >> 4, c4 = (idx & 15) << 2;
        float4 v = *(float4*)&Cs[r * C_STR + c4];
        v.x += bo[col0 + c4 + 0];
        v.y += bo[col0 + c4 + 1];
        v.z += bo[col0 + c4 + 2];
        v.w += bo[col0 + c4 + 3];
        *(float4*)&y[(row0 + r) * Dm + col0 + c4] = v;
    }
}

// ---------------------------------------------------------------------------
extern "C" void kernel_launch(void* const* d_in, const int* in_sizes, int n_in,
                              void* d_out, int out_size)
{
    const float* x  = (const float*)d_in[0];
    const float* Wq = (const float*)d_in[1];
    const float* bq = (const float*)d_in[2];
    const float* Wk = (const float*)d_in[3];
    const float* bk = (const float*)d_in[4];
    const float* Wv = (const float*)d_in[5];
    const float* bv = (const float*)d_in[6];
    const float* Wo = (const float*)d_in[7];
    const float* bo = (const float*)d_in[8];
    float* y = (float*)d_out;

    cudaFuncSetAttribute(qkv_mma_kernel,
                         cudaFuncAttributeMaxDynamicSharedMemorySize, GEMM_SMEM);
    cudaFuncSetAttribute(out_mma_kernel,
                         cudaFuncAttributeMaxDynamicSharedMemorySize, GEMM_SMEM);
    cudaFuncSetAttribute(chunk_mma_kernel,
                         cudaFuncAttributeMaxDynamicSharedMemorySize, CHUNK_SMEM);
    cudaFuncSetAttribute(attn_kernel,
                         cudaFuncAttributeMaxDynamicSharedMemorySize, ATTN_SMEM);

    qkv_mma_kernel  <<<dim3(T/128, H, 3), 256, GEMM_SMEM>>>(x, Wq, bq, Wk, bk, Wv, bv);
    chunk_mma_kernel<<<dim3(NC, H), 256, CHUNK_SMEM>>>();
    prefix_kernel   <<<dim3(H, (STATS_STRIDE + 255) / 256), 256>>>();
    attn_kernel     <<<dim3(NC, H), 256, ATTN_SMEM>>>();
    out_mma_kernel  <<<dim3(T/128, Dm/64), 256, GEMM_SMEM>>>(Wo, bo, y);
}

// round 7
// speedup vs baseline: 3.1612x; 1.5399x over previous
#include <cuda_runtime.h>
#include <cuda_bf16.h>
#include <math.h>
#include <stdint.h>

// Problem constants
#define T   2048
#define Dm  512
#define H   8
#define DH  64
#define CH  128
#define NC  (T / CH)
#define STATS_STRIDE (DH*DH + DH)   // 4160

// Scratch (device globals — no allocation allowed)
__device__ float g_Qp[H * T * DH];
__device__ float g_Kp[H * T * DH];
__device__ float g_V [H * T * DH];
__device__ float g_stats[H * NC * STATS_STRIDE];
__device__ float g_pref [H * NC * STATS_STRIDE];   // transposed KV + ksum @4096
// Pre-split bf16 planes (packed as uint32 = 2 bf16)
__device__ uint32_t g_xhi[T * Dm / 2], g_xlo[T * Dm / 2];     // x, row-major [t][k]
__device__ uint32_t g_whi[4 * Dm * Dm / 2], g_wlo[4 * Dm * Dm / 2]; // W^T [m][n][k]
__device__ uint32_t g_Ohi[T * Dm / 2], g_Olo[T * Dm / 2];     // attn out [t][n]

// ===========================================================================
// Helpers
// ===========================================================================
__device__ __forceinline__ uint32_t pack_bf2(float a, float b) {
    __nv_bfloat162 t;
    t.x = __float2bfloat16_rn(a);
    t.y = __float2bfloat16_rn(b);
    return *(uint32_t*)&t;
}
__device__ __forceinline__ float bfr(float x) {
    return __bfloat162float(__float2bfloat16_rn(x));
}
__device__ __forceinline__ void mma16(float c[4], const uint32_t a[4], const uint32_t b[2]) {
    asm volatile(
        "mma.sync.aligned.m16n8k16.row.col.f32.bf16.bf16.f32 "
        "{%0,%1,%2,%3}, {%4,%5,%6,%7}, {%8,%9}, {%0,%1,%2,%3};"
        : "+f"(c[0]), "+f"(c[1]), "+f"(c[2]), "+f"(c[3])
        : "r"(a[0]), "r"(a[1]), "r"(a[2]), "r"(a[3]),
          "r"(b[0]), "r"(b[1]));
}
__device__ __forceinline__ uint32_t smem_u32(const void* p) {
    uint32_t a;
    asm("{ .reg .u64 t; cvta.to.shared.u64 t, %1; cvt.u32.u64 %0, t; }"
        : "=r"(a) : "l"(p));
    return a;
}
__device__ __forceinline__ void ldm_x4(uint32_t* r, uint32_t addr) {
    asm volatile("ldmatrix.sync.aligned.m8n8.x4.shared.b16 {%0,%1,%2,%3}, [%4];"
        : "=r"(r[0]), "=r"(r[1]), "=r"(r[2]), "=r"(r[3]) : "r"(addr));
}
__device__ __forceinline__ void cp16(uint32_t dst, const void* src) {
    asm volatile("cp.async.cg.shared.global [%0], [%1], 16;" :: "r"(dst), "l"(src));
}
#define CP_COMMIT() asm volatile("cp.async.commit_group;" ::: "memory")
#define CP_WAIT0()  asm volatile("cp.async.wait_group 0;" ::: "memory")

// ===========================================================================
// Prep kernels: split weights (with transpose) and x into bf16 hi/lo planes.
// ===========================================================================
__global__ void wsplit_kernel(const float* __restrict__ Wq, const float* __restrict__ Wk,
                              const float* __restrict__ Wv, const float* __restrict__ Wo)
{
    __shared__ float tile[32][33];
    const int m = blockIdx.z;
    const float* W = (m == 0) ? Wq : (m == 1) ? Wk : (m == 2) ? Wv : Wo;
    const int kb = blockIdx.x * 32, nb = blockIdx.y * 32;
    const int tid = threadIdx.x;
    const int tr = tid >> 5, tc = tid & 31;
    #pragma unroll
    for (int i = 0; i < 4; i++)
        tile[tr + i * 8][tc] = W[(kb + tr + i * 8) * Dm + nb + tc];
    __syncthreads();
    const int nr = tid >> 4, k2 = (tid & 15) * 2;
    #pragma unroll
    for (int i = 0; i < 2; i++) {
        int n = nr + i * 16;
        float v0 = tile[k2][n], v1 = tile[k2 + 1][n];
        float h0 = bfr(v0), h1 = bfr(v1);
        int widx = m * (Dm * Dm / 2) + (nb + n) * (Dm / 2) + ((kb + k2) >> 1);
        g_whi[widx] = pack_bf2(h0, h1);
        g_wlo[widx] = pack_bf2(v0 - h0, v1 - h1);
    }
}

__global__ void xsplit_kernel(const float* __restrict__ x)
{
    int idx = blockIdx.x * 256 + threadIdx.x;    // 262144 float4
    float4 v = ((const float4*)x)[idx];
    float h0 = bfr(v.x), h1 = bfr(v.y), h2 = bfr(v.z), h3 = bfr(v.w);
    ((uint2*)g_xhi)[idx] = make_uint2(pack_bf2(h0, h1), pack_bf2(h2, h3));
    ((uint2*)g_xlo)[idx] = make_uint2(pack_bf2(v.x - h0, v.y - h1),
                                      pack_bf2(v.z - h2, v.w - h3));
}

// ===========================================================================
// GEMM: bf16 3-term split, cp.async double-buffered, ldmatrix fragments.
// Tile BM=128, BN=64, BK=64 (8 slabs over K=512). 256 thr = 8 warps (4Mx2N).
// smem/buffer: A_hi 16K | A_lo 16K | B_hi 8K | B_lo 8K = 48K; x2 = 96K.
// 128B rows with XOR-16B-group swizzle (group ^= row&7).
// ===========================================================================
#define GB_BUF 49152
#define GEMM_SMEM (2 * GB_BUF)
#define C_STR 68

__device__ __forceinline__ void gemm_tc(char* smem,
    const char* Ahi, const char* Alo, const char* Bhi, const char* Blo,
    int row0, int col0, float acc[2][4][4])
{
    const int tid = threadIdx.x, lane = tid & 31, wid = tid >> 5;
    const int wm = (wid & 3) * 32, wn = (wid >> 2) * 32;
    uint32_t sb = smem_u32(smem);

    #pragma unroll
    for (int mt = 0; mt < 2; mt++)
        #pragma unroll
        for (int nt = 0; nt < 4; nt++)
            #pragma unroll
            for (int i = 0; i < 4; i++) acc[mt][nt][i] = 0.f;

    // staging maps (constant per thread)
    uint32_t smA[8]; const char* gA[8];
    #pragma unroll
    for (int i = 0; i < 8; i++) {
        int c = tid + i * 256;
        int plane = c >> 10, rc = c & 1023, r = rc >> 3, g = rc & 7;
        smA[i] = plane * 16384 + r * 128 + ((g ^ (r & 7)) << 4);
        gA[i] = (plane ? Alo : Ahi) + (size_t)(row0 + r) * 1024 + g * 16;
    }
    uint32_t smB[4]; const char* gB[4];
    #pragma unroll
    for (int i = 0; i < 4; i++) {
        int c = tid + i * 256;
        int plane = c >> 9, rc = c & 511, n = rc >> 3, g = rc & 7;
        smB[i] = 32768 + plane * 8192 + n * 128 + ((g ^ (n & 7)) << 4);
        gB[i] = (plane ? Blo : Bhi) + (size_t)(col0 + n) * 1024 + g * 16;
    }

    // prologue: slab 0
    #pragma unroll
    for (int i = 0; i < 8; i++) cp16(sb + smA[i], gA[i]);
    #pragma unroll
    for (int i = 0; i < 4; i++) cp16(sb + smB[i], gB[i]);
    CP_COMMIT();

    const int rA = wm + (lane & 15);          // A frag row (mt adds +16)
    const int nB = wn + (lane & 15);          // B frag row (pair adds +16)
    const int seg = lane >> 4;
    const int xv = lane & 7;                  // swizzle xor (row&7 == lane&7)

    for (int s = 0; s < 8; s++) {
        CP_WAIT0();
        __syncthreads();
        if (s + 1 < 8) {
            int koff = (s + 1) * 128;
            uint32_t boff = (uint32_t)(((s + 1) & 1) * GB_BUF);
            #pragma unroll
            for (int i = 0; i < 8; i++) cp16(sb + boff + smA[i], gA[i] + koff);
            #pragma unroll
            for (int i = 0; i < 4; i++) cp16(sb + boff + smB[i], gB[i] + koff);
            CP_COMMIT();
        }
        uint32_t bufb = sb + (uint32_t)((s & 1) * GB_BUF);

        #pragma unroll
        for (int ks = 0; ks < 4; ks++) {
            uint32_t sw = (uint32_t)((((ks << 1) + seg) ^ xv) << 4);
            uint32_t ah[2][4], al[2][4];
            {
                uint32_t a0 = bufb + rA * 128 + sw;
                ldm_x4(ah[0], a0);
                ldm_x4(al[0], a0 + 16384);
                uint32_t a1 = a0 + 16 * 128;
                ldm_x4(ah[1], a1);
                ldm_x4(al[1], a1 + 16384);
            }
            uint32_t q[4], bh[4][2], bl[4][2];
            {
                uint32_t b0 = bufb + 32768 + nB * 128 + sw;
                ldm_x4(q, b0);
                bh[0][0] = q[0]; bh[0][1] = q[2]; bh[1][0] = q[1]; bh[1][1] = q[3];
                ldm_x4(q, b0 + 8192);
                bl[0][0] = q[0]; bl[0][1] = q[2]; bl[1][0] = q[1]; bl[1][1] = q[3];
                uint32_t b1 = b0 + 16 * 128;
                ldm_x4(q, b1);
                bh[2][0] = q[0]; bh[2][1] = q[2]; bh[3][0] = q[1]; bh[3][1] = q[3];
                ldm_x4(q, b1 + 8192);
                bl[2][0] = q[0]; bl[2][1] = q[2]; bl[3][0] = q[1]; bl[3][1] = q[3];
            }
            #pragma unroll
            for (int mt = 0; mt < 2; mt++)
                #pragma unroll
                for (int nt = 0; nt < 4; nt++) {
                    mma16(acc[mt][nt], ah[mt], bh[nt]);
                    mma16(acc[mt][nt], al[mt], bh[nt]);
                    mma16(acc[mt][nt], ah[mt], bl[nt]);
                }
        }
    }
}

__device__ __forceinline__ void acc_to_smem(float* Cs, const float acc[2][4][4])
{
    const int lane = threadIdx.x & 31;
    const int wid  = threadIdx.x >> 5;
    const int wm   = (wid & 3) * 32;
    const int wn   = (wid >> 2) * 32;
    const int lr = lane >> 2, lc = lane & 3;

    #pragma unroll
    for (int mt = 0; mt < 2; mt++)
        #pragma unroll
        for (int nt = 0; nt < 4; nt++) {
            int r = wm + mt * 16 + lr;
            int n = wn + nt * 8 + 2 * lc;
            #pragma unroll
            for (int i = 0; i < 4; i++)
                Cs[(r + (i >= 2 ? 8 : 0)) * C_STR + n + (i & 1)] = acc[mt][nt][i];
        }
}

// ---------------------------------------------------------------------------
// Kernel 1: fused QKV projection. grid = (T/128, H, 3).
// ---------------------------------------------------------------------------
__global__ void __launch_bounds__(256, 2) qkv_tc_kernel(
    const float* __restrict__ bq, const float* __restrict__ bk,
    const float* __restrict__ bv)
{
    extern __shared__ char smem[];

    const int which = blockIdx.z;
    const float* b = (which == 0) ? bq : (which == 1) ? bk : bv;
    float* out = (which == 0) ? g_Qp : (which == 1) ? g_Kp : g_V;

    const int row0 = blockIdx.x * 128;
    const int h    = blockIdx.y;
    const int col0 = h * 64;

    float acc[2][4][4];
    gemm_tc(smem, (const char*)g_xhi, (const char*)g_xlo,
            (const char*)(g_whi + which * (Dm * Dm / 2)),
            (const char*)(g_wlo + which * (Dm * Dm / 2)),
            row0, col0, acc);

    float* Cs = (float*)smem;
    acc_to_smem(Cs, acc);
    __syncthreads();

    const int tid = threadIdx.x;
    #pragma unroll
    for (int it = 0; it < 8; it++) {
        int idx = tid + it * 256;
        int r = idx >> 4, c4 = (idx & 15) << 2;
        float4 v = *(float4*)&Cs[r * C_STR + c4];
        v.x += b[col0 + c4 + 0];
        v.y += b[col0 + c4 + 1];
        v.z += b[col0 + c4 + 2];
        v.w += b[col0 + c4 + 3];
        if (which < 2) {
            v.x = (v.x > 0.f) ? (v.x + 1.f) : expf(v.x);
            v.y = (v.y > 0.f) ? (v.y + 1.f) : expf(v.y);
            v.z = (v.z > 0.f) ? (v.z + 1.f) : expf(v.z);
            v.w = (v.w > 0.f) ? (v.w + 1.f) : expf(v.w);
        }
        *(float4*)&out[((h * T + row0 + r) << 6) + c4] = v;
    }
}

// ---------------------------------------------------------------------------
// Kernel 5: output projection. grid = (T/128, Dm/64).
// ---------------------------------------------------------------------------
__global__ void __launch_bounds__(256, 2) out_tc_kernel(
    const float* __restrict__ bo, float* __restrict__ y)
{
    extern __shared__ char smem[];

    const int row0 = blockIdx.x * 128;
    const int col0 = blockIdx.y * 64;

    float acc[2][4][4];
    gemm_tc(smem, (const char*)g_Ohi, (const char*)g_Olo,
            (const char*)(g_whi + 3 * (Dm * Dm / 2)),
            (const char*)(g_wlo + 3 * (Dm * Dm / 2)),
            row0, col0, acc);

    float* Cs = (float*)smem;
    acc_to_smem(Cs, acc);
    __syncthreads();

    const int tid = threadIdx.x;
    #pragma unroll
    for (int it = 0; it < 8; it++) {
        int idx = tid + it * 256;
        int r = idx >> 4, c4 = (idx & 15) << 2;
        float4 v = *(float4*)&Cs[r * C_STR + c4];
        v.x += bo[col0 + c4 + 0];
        v.y += bo[col0 + c4 + 1];
        v.z += bo[col0 + c4 + 2];
        v.w += bo[col0 + c4 + 3];
        *(float4*)&y[(row0 + r) * Dm + col0 + c4] = v;
    }
}

// ===========================================================================
// Staging helpers for attn/chunk kernels (legacy LDS fragments; from R5)
// ===========================================================================
__device__ __forceinline__ void stage_rowmajor(uint32_t* smw, int offH, int offL,
                                               const float* __restrict__ src,
                                               int rows, int tid)
{
    int iters = rows >> 4;
    for (int i = 0; i < iters; i++) {
        int slot = tid + i * 256;
        int r = slot >> 4, c4 = (slot & 15) << 2;
        float4 v = *(const float4*)&src[(r << 6) + c4];
        float h0 = bfr(v.x), h1 = bfr(v.y), h2 = bfr(v.z), h3 = bfr(v.w);
        int w = r * 36 + (c4 >> 1);
        *(uint2*)(smw + offH + w) = make_uint2(pack_bf2(h0, h1), pack_bf2(h2, h3));
        *(uint2*)(smw + offL + w) = make_uint2(pack_bf2(v.x - h0, v.y - h1),
                                               pack_bf2(v.z - h2, v.w - h3));
    }
}

__device__ __forceinline__ float stage_transposed(uint32_t* smw, int offH, int offL,
                                                  const float* __restrict__ src, int tid)
{
    int d = tid & 63, tb = tid >> 6;
    int sw = (d >> 3) & 3;
    const float* col = src + d;
    uint32_t* ph = smw + offH + d * 68;
    uint32_t* pl = smw + offL + d * 68;
    float s = 0.f;
    #pragma unroll
    for (int u2 = 0; u2 < 16; u2++) {
        int t = tb * 32 + u2 * 2;
        float v0 = col[t << 6];
        float v1 = col[(t + 1) << 6];
        s += v0 + v1;
        float h0 = bfr(v0), h1 = bfr(v1);
        int w = (tb * 16 + u2) ^ sw;
        ph[w] = pack_bf2(h0, h1);
        pl[w] = pack_bf2(v0 - h0, v1 - h1);
    }
    return s;
}

// ===========================================================================
// Kernel 2: chunk stats (tensor cores, unchanged from R5).
// ===========================================================================
#define CK_KH 0
#define CK_KL (64*68)
#define CK_VH (2*64*68)
#define CK_VL (3*64*68)
#define CK_PART (4*64*68)
#define CHUNK_SMEM ((CK_PART + 256) * 4)

__global__ void __launch_bounds__(256, 1) chunk_mma_kernel()
{
    extern __shared__ uint32_t smw[];
    float* kpart = (float*)(smw + CK_PART);

    const int c = blockIdx.x, h = blockIdx.y;
    const int tid = threadIdx.x;
    const float* Kbase = g_Kp + ((h * T + c * CH) << 6);
    const float* Vbase = g_V  + ((h * T + c * CH) << 6);

    float ks = stage_transposed(smw, CK_KH, CK_KL, Kbase, tid);
    kpart[(tid >> 6) * 64 + (tid & 63)] = ks;
    stage_transposed(smw, CK_VH, CK_VL, Vbase, tid);
    __syncthreads();

    const int lane = tid & 31, wid = tid >> 5;
    const int lr = lane >> 2, lc = lane & 3;
    const int wm = (wid & 3) * 16;
    const int wn = (wid >> 2) * 32;
    const int i0 = wm + lr, i1 = i0 + 8;

    uint32_t ah[8][4], al[8][4];
    {
        const int sw0 = (i0 >> 3) & 3;
        const int sw1 = (i1 >> 3) & 3;
        const uint32_t* h0 = smw + CK_KH + i0 * 68;
        const uint32_t* h1 = smw + CK_KH + i1 * 68;
        const uint32_t* l0 = smw + CK_KL + i0 * 68;
        const uint32_t* l1 = smw + CK_KL + i1 * 68;
        #pragma unroll
        for (int kh = 0; kh < 8; kh++) {
            int w0 = (kh * 8 + lc) ^ sw0;
            int w1 = (kh * 8 + lc) ^ sw1;
            ah[kh][0] = h0[w0];     ah[kh][1] = h1[w1];
            ah[kh][2] = h0[w0 + 4]; ah[kh][3] = h1[w1 + 4];
            al[kh][0] = l0[w0];     al[kh][1] = l1[w1];
            al[kh][2] = l0[w0 + 4]; al[kh][3] = l1[w1 + 4];
        }
    }

    float cb[4][4];
    #pragma unroll
    for (int nt = 0; nt < 4; nt++)
        #pragma unroll
        for (int i = 0; i < 4; i++) cb[nt][i] = 0.f;

    #pragma unroll
    for (int nt = 0; nt < 4; nt++) {
        int n = wn + nt * 8 + lr;
        int swB = (n >> 3) & 3;
        const uint32_t* vh = smw + CK_VH + n * 68;
        const uint32_t* vl = smw + CK_VL + n * 68;
        #pragma unroll
        for (int kh = 0; kh < 8; kh++) {
            int w = (kh * 8 + lc) ^ swB;
            uint32_t bh[2] = {vh[w], vh[w + 4]};
            uint32_t bl[2] = {vl[w], vl[w + 4]};
            mma16(cb[nt], ah[kh], bh);
            mma16(cb[nt], al[kh], bh);
            mma16(cb[nt], ah[kh], bl);
        }
    }

    float* outp = g_stats + (h * NC + c) * STATS_STRIDE;
    #pragma unroll
    for (int nt = 0; nt < 4; nt++) {
        int j0 = wn + nt * 8 + 2 * lc;
        *(float2*)&outp[i0 * 64 + j0] = make_float2(cb[nt][0], cb[nt][1]);
        *(float2*)&outp[i1 * 64 + j0] = make_float2(cb[nt][2], cb[nt][3]);
    }
    if (tid < 64)
        outp[4096 + tid] = kpart[tid] + kpart[64 + tid] + kpart[128 + tid] + kpart[192 + tid];
}

// ---------------------------------------------------------------------------
// Kernel 3: exclusive prefix over chunks (transposed KV), unchanged.
// ---------------------------------------------------------------------------
__global__ void prefix_kernel()
{
    const int hh = blockIdx.x;
    const int e = blockIdx.y * 256 + threadIdx.x;
    if (e >= STATS_STRIDE) return;

    int src_e;
    if (e < 4096) {
        int j = e >> 6, i = e & 63;
        src_e = i * 64 + j;
    } else {
        src_e = e;
    }

    float v[NC];
    #pragma unroll
    for (int c = 0; c < NC; c++)
        v[c] = g_stats[(hh * NC + c) * STATS_STRIDE + src_e];

    float run = 0.f;
    #pragma unroll
    for (int c = 0; c < NC; c++) {
        g_pref[(hh * NC + c) * STATS_STRIDE + e] = run;
        run += v[c];
    }
}

// ===========================================================================
// Kernel 4: attention (tensor cores, from R5; epilogue now writes SPLIT O).
// ===========================================================================
#define OFF_QH 0
#define OFF_QL (OFF_QH + 128*36)
#define OFF_KH (OFF_QL + 128*36)
#define OFF_KL (OFF_KH + 128*36)
#define OFF_VH (OFF_KL + 128*36)
#define OFF_VL (OFF_VH + 64*68)
#define OFF_SH (OFF_VL + 64*68)
#define OFF_SL (OFF_SH + 72*36)
#define OFF_AH (OFF_SL + 72*36)
#define OFF_AL (OFF_AH + 128*68)
#define ATTN_SMEM ((OFF_AL + 128*68) * 4)

__global__ void __launch_bounds__(256, 1) attn_kernel()
{
    extern __shared__ uint32_t smw[];

    const int c = blockIdx.x, h = blockIdx.y;
    const int tid = threadIdx.x;
    const float* Qbase = g_Qp + ((h * T + c * CH) << 6);
    const float* Kbase = g_Kp + ((h * T + c * CH) << 6);
    const float* Vbase = g_V  + ((h * T + c * CH) << 6);
    const float* P     = g_pref + (h * NC + c) * STATS_STRIDE;

    stage_rowmajor(smw, OFF_QH, OFF_QL, Qbase, 128, tid);
    stage_rowmajor(smw, OFF_KH, OFF_KL, Kbase, 128, tid);
    stage_rowmajor(smw, OFF_SH, OFF_SL, P, 64, tid);
    stage_transposed(smw, OFF_VH, OFF_VL, Vbase, tid);
    if (tid < 128) {
        int r = 64 + (tid >> 4), c4 = (tid & 15) << 2;
        float4 v = make_float4(0.f, 0.f, 0.f, 0.f);
        if (r == 64) v = *(const float4*)&P[4096 + c4];
        float h0 = bfr(v.x), h1 = bfr(v.y), h2 = bfr(v.z), h3 = bfr(v.w);
        int w = r * 36 + (c4 >> 1);
        *(uint2*)(smw + OFF_SH + w) = make_uint2(pack_bf2(h0, h1), pack_bf2(h2, h3));
        *(uint2*)(smw + OFF_SL + w) = make_uint2(pack_bf2(v.x - h0, v.y - h1),
                                                 pack_bf2(v.z - h2, v.w - h3));
    }
    __syncthreads();

    const int lane = tid & 31, wid = tid >> 5;
    const int lr = lane >> 2, lc = lane & 3;
    const int wm = wid * 16;
    const int t0 = wm + lr, t1 = t0 + 8;

    uint32_t qh[4][4], ql[4][4];
    {
        const uint32_t* ph = smw + OFF_QH + t0 * 36 + lc;
        const uint32_t* pl = smw + OFF_QL + t0 * 36 + lc;
        #pragma unroll
        for (int kh = 0; kh < 4; kh++) {
            int o = kh * 8;
            qh[kh][0] = ph[o];     qh[kh][1] = ph[o + 288];
            qh[kh][2] = ph[o + 4]; qh[kh][3] = ph[o + 292];
            ql[kh][0] = pl[o];     ql[kh][1] = pl[o + 288];
            ql[kh][2] = pl[o + 4]; ql[kh][3] = pl[o + 292];
        }
    }

    float ca[16][4];
    #pragma unroll
    for (int nt = 0; nt < 16; nt++)
        #pragma unroll
        for (int i = 0; i < 4; i++) ca[nt][i] = 0.f;

    #pragma unroll
    for (int nt = 0; nt < 16; nt++) {
        const uint32_t* bhp = smw + OFF_KH + (nt * 8 + lr) * 36 + lc;
        const uint32_t* blp = smw + OFF_KL + (nt * 8 + lr) * 36 + lc;
        #pragma unroll
        for (int kh = 0; kh < 4; kh++) {
            uint32_t bh[2] = {bhp[kh * 8], bhp[kh * 8 + 4]};
            uint32_t bl[2] = {blp[kh * 8], blp[kh * 8 + 4]};
            mma16(ca[nt], qh[kh], bh);
            mma16(ca[nt], ql[kh], bh);
            mma16(ca[nt], qh[kh], bl);
        }
    }

    float rs0 = 0.f, rs1 = 0.f;
    #pragma unroll
    for (int nt = 0; nt < 16; nt++) {
        int s0 = nt * 8 + 2 * lc;
        float c0 = (s0     <= t0) ? ca[nt][0] : 0.f;
        float c1 = (s0 + 1 <= t0) ? ca[nt][1] : 0.f;
        float c2 = (s0     <= t1) ? ca[nt][2] : 0.f;
        float c3 = (s0 + 1 <= t1) ? ca[nt][3] : 0.f;
        rs0 += c0 + c1;
        rs1 += c2 + c3;
        float h0 = bfr(c0), h1 = bfr(c1), h2 = bfr(c2), h3 = bfr(c3);
        int w = nt * 4 + lc;
        smw[OFF_AH + t0 * 68 + w] = pack_bf2(h0, h1);
        smw[OFF_AL + t0 * 68 + w] = pack_bf2(c0 - h0, c1 - h1);
        smw[OFF_AH + t1 * 68 + w] = pack_bf2(h2, h3);
        smw[OFF_AL + t1 * 68 + w] = pack_bf2(c2 - h2, c3 - h3);
    }
    rs0 += __shfl_xor_sync(0xffffffffu, rs0, 1);
    rs0 += __shfl_xor_sync(0xffffffffu, rs0, 2);
    rs1 += __shfl_xor_sync(0xffffffffu, rs1, 1);
    rs1 += __shfl_xor_sync(0xffffffffu, rs1, 2);
    __syncthreads();

    uint32_t aAh[8][4], aAl[8][4];
    {
        const uint32_t* ph = smw + OFF_AH + t0 * 68 + lc;
        const uint32_t* pl = smw + OFF_AL + t0 * 68 + lc;
        #pragma unroll
        for (int kh = 0; kh < 8; kh++) {
            int o = kh * 8;
            aAh[kh][0] = ph[o];     aAh[kh][1] = ph[o + 544];
            aAh[kh][2] = ph[o + 4]; aAh[kh][3] = ph[o + 548];
            aAl[kh][0] = pl[o];     aAl[kh][1] = pl[o + 544];
            aAl[kh][2] = pl[o + 4]; aAl[kh][3] = pl[o + 548];
        }
    }

    float cb[9][4];
    #pragma unroll
    for (int nt = 0; nt < 9; nt++)
        #pragma unroll
        for (int i = 0; i < 4; i++) cb[nt][i] = 0.f;

    #pragma unroll
    for (int nt = 0; nt < 8; nt++) {
        int n = nt * 8 + lr;
        int swB = nt & 3;
        const uint32_t* vh = smw + OFF_VH + n * 68;
        const uint32_t* vl = smw + OFF_VL + n * 68;
        #pragma unroll
        for (int kh = 0; kh < 8; kh++) {
            int w = (kh * 8 + lc) ^ swB;
            uint32_t bh[2] = {vh[w], vh[w + 4]};
            uint32_t bl[2] = {vl[w], vl[w + 4]};
            mma16(cb[nt], aAh[kh], bh);
            mma16(cb[nt], aAl[kh], bh);
            mma16(cb[nt], aAh[kh], bl);
        }
        const uint32_t* sh = smw + OFF_SH + n * 36 + lc;
        const uint32_t* sl = smw + OFF_SL + n * 36 + lc;
        #pragma unroll
        for (int ks = 0; ks < 4; ks++) {
            uint32_t bh[2] = {sh[ks * 8], sh[ks * 8 + 4]};
            uint32_t bl[2] = {sl[ks * 8], sl[ks * 8 + 4]};
            mma16(cb[nt], qh[ks], bh);
            mma16(cb[nt], ql[ks], bh);
            mma16(cb[nt], qh[ks], bl);
        }
    }
    {
        int n = 64 + lr;
        const uint32_t* sh = smw + OFF_SH + n * 36 + lc;
        const uint32_t* sl = smw + OFF_SL + n * 36 + lc;
        #pragma unroll
        for (int ks = 0; ks < 4; ks++) {
            uint32_t bh[2] = {sh[ks * 8], sh[ks * 8 + 4]};
            uint32_t bl[2] = {sl[ks * 8], sl[ks * 8 + 4]};
            mma16(cb[8], qh[ks], bh);
            mma16(cb[8], ql[ks], bh);
            mma16(cb[8], qh[ks], bl);
        }
    }

    float di0 = __shfl_sync(0xffffffffu, cb[8][0], lane & ~3);
    float di1 = __shfl_sync(0xffffffffu, cb[8][2], lane & ~3);
    float inv0 = 1.f / fmaxf(rs0 + di0, 1e-6f);
    float inv1 = 1.f / fmaxf(rs1 + di1, 1e-6f);

    // Split write: O row-major [t][512] bf16 hi/lo (word = 2 cols)
    const int base = (c * CH) * (Dm / 2) + h * 32;
    #pragma unroll
    for (int nt = 0; nt < 8; nt++) {
        int jw = (nt * 8 + 2 * lc) >> 1;
        {
            float o0 = cb[nt][0] * inv0, o1 = cb[nt][1] * inv0;
            float h0 = bfr(o0), h1 = bfr(o1);
            g_Ohi[base + t0 * (Dm / 2) + jw] = pack_bf2(h0, h1);
            g_Olo[base + t0 * (Dm / 2) + jw] = pack_bf2(o0 - h0, o1 - h1);
        }
        {
            float o0 = cb[nt][2] * inv1, o1 = cb[nt][3] * inv1;
            float h0 = bfr(o0), h1 = bfr(o1);
            g_Ohi[base + t1 * (Dm / 2) + jw] = pack_bf2(h0, h1);
            g_Olo[base + t1 * (Dm / 2) + jw] = pack_bf2(o0 - h0, o1 - h1);
        }
    }
}

// ---------------------------------------------------------------------------
extern "C" void kernel_launch(void* const* d_in, const int* in_sizes, int n_in,
                              void* d_out, int out_size)
{
    const float* x  = (const float*)d_in[0];
    const float* Wq = (const float*)d_in[1];
    const float* bq = (const float*)d_in[2];
    const float* Wk = (const float*)d_in[3];
    const float* bk = (const float*)d_in[4];
    const float* Wv = (const float*)d_in[5];
    const float* bv = (const float*)d_in[6];
    const float* Wo = (const float*)d_in[7];
    const float* bo = (const float*)d_in[8];
    float* y = (float*)d_out;

    cudaFuncSetAttribute(qkv_tc_kernel,
                         cudaFuncAttributeMaxDynamicSharedMemorySize, GEMM_SMEM);
    cudaFuncSetAttribute(out_tc_kernel,
                         cudaFuncAttributeMaxDynamicSharedMemorySize, GEMM_SMEM);
    cudaFuncSetAttribute(chunk_mma_kernel,
                         cudaFuncAttributeMaxDynamicSharedMemorySize, CHUNK_SMEM);
    cudaFuncSetAttribute(attn_kernel,
                         cudaFuncAttributeMaxDynamicSharedMemorySize, ATTN_SMEM);

    wsplit_kernel   <<<dim3(16, 16, 4), 256>>>(Wq, Wk, Wv, Wo);
    xsplit_kernel   <<<1024, 256>>>(x);
    qkv_tc_kernel   <<<dim3(T/128, H, 3), 256, GEMM_SMEM>>>(bq, bk, bv);
    chunk_mma_kernel<<<dim3(NC, H), 256, CHUNK_SMEM>>>();
    prefix_kernel   <<<dim3(H, (STATS_STRIDE + 255) / 256), 256>>>();
    attn_kernel     <<<dim3(NC, H), 256, ATTN_SMEM>>>();
    out_tc_kernel   <<<dim3(T/128, Dm/64), 256, GEMM_SMEM>>>(bo, y);
}